// round 1
// baseline (speedup 1.0000x reference)
#include <cuda_runtime.h>
#include <math.h>

#define NB 2
#define NH 16
#define SEQ 2048
#define DH 128
#define DM 2048          // NH*DH
#define MTOK (NB*SEQ)    // 4096

// Scratch (static device allocations — allowed; no cudaMalloc anywhere)
__device__ float g_qkvh[(size_t)3 * NB * NH * SEQ * DH];  // [3][B][H][S][D] ~100MB
__device__ float g_ctx[(size_t)MTOK * DM];                // [B*S][DM] ~33MB

// ---------------------------------------------------------------------------
// GEMM 1: qkv = x @ W_qkv + b_qkv, scattered into head-major layout
// x: [4096, 2048], W_qkv: [2048, 6144]
// ---------------------------------------------------------------------------
__global__ __launch_bounds__(256, 2) void gemm_qkv_kernel(
    const float* __restrict__ A, const float* __restrict__ Bw,
    const float* __restrict__ bias) {
  const int K = DM, N = 3 * DM;
  __shared__ float As[16][132];
  __shared__ float Bs[16][132];
  const int bm = blockIdx.y * 128, bn = blockIdx.x * 128;
  const int tid = threadIdx.x;
  const int tx = tid & 15, ty = tid >> 4;
  float acc[8][8];
#pragma unroll
  for (int i = 0; i < 8; i++)
#pragma unroll
    for (int j = 0; j < 8; j++) acc[i][j] = 0.f;

  for (int k0 = 0; k0 < K; k0 += 16) {
#pragma unroll
    for (int i = 0; i < 2; i++) {
      int s = tid + i * 256;
      int row = s >> 2, c4 = (s & 3) * 4;
      float4 v = *(const float4*)(A + (size_t)(bm + row) * K + k0 + c4);
      As[c4 + 0][row] = v.x; As[c4 + 1][row] = v.y;
      As[c4 + 2][row] = v.z; As[c4 + 3][row] = v.w;
    }
#pragma unroll
    for (int i = 0; i < 2; i++) {
      int s = tid + i * 256;
      int row = s >> 5, c4 = (s & 31) * 4;
      *(float4*)(&Bs[row][c4]) =
          *(const float4*)(Bw + (size_t)(k0 + row) * N + bn + c4);
    }
    __syncthreads();
#pragma unroll
    for (int kk = 0; kk < 16; kk++) {
      float a[8], b[8];
      *(float4*)(a)     = *(float4*)(&As[kk][ty * 8]);
      *(float4*)(a + 4) = *(float4*)(&As[kk][ty * 8 + 4]);
      *(float4*)(b)     = *(float4*)(&Bs[kk][tx * 8]);
      *(float4*)(b + 4) = *(float4*)(&Bs[kk][tx * 8 + 4]);
#pragma unroll
      for (int i = 0; i < 8; i++)
#pragma unroll
        for (int j = 0; j < 8; j++) acc[i][j] += a[i] * b[j];
    }
    __syncthreads();
  }
#pragma unroll
  for (int i = 0; i < 8; i++) {
    int m = bm + ty * 8 + i;
    int b = m >> 11, sidx = m & 2047;
#pragma unroll
    for (int j = 0; j < 8; j++) {
      int n = bn + tx * 8 + j;
      float val = acc[i][j] + bias[n];
      int which = n >> 11, r = n & 2047;
      int h = r >> 7, d = r & 127;
      g_qkvh[(size_t)(((which * NB + b) * NH + h) * SEQ + sidx) * DH + d] = val;
    }
  }
}

// ---------------------------------------------------------------------------
// Flash attention: causal, online softmax. Grid: (q_tiles=32, B*H=32), 256 thr.
// Tiles: 64 q-rows x 64 k-cols, D=128. Dynamic smem 120832 B.
// ---------------------------------------------------------------------------
__global__ __launch_bounds__(256) void flash_kernel() {
  extern __shared__ float sm[];
  float* QsT = sm;                 // [128][68] (d-major)
  float* KsT = sm + 128 * 68;      // [128][68]
  float* Vs  = sm + 2 * 128 * 68;  // [64][132]
  float* PsT = Vs + 64 * 132;      // [64 kk][68 rows]
  const int bh = blockIdx.y;
  const int qt = blockIdx.x;
  const float* Qg = g_qkvh + (size_t)bh * SEQ * DH;
  const float* Kg = g_qkvh + (size_t)(32 + bh) * SEQ * DH;
  const float* Vg = g_qkvh + (size_t)(64 + bh) * SEQ * DH;
  const int q0 = qt * 64;
  const int tid = threadIdx.x, tx = tid & 15, ty = tid >> 4;

  // Load Q tile, transposed to d-major
#pragma unroll
  for (int i = 0; i < 8; i++) {
    int s = tid + i * 256;
    int r = s >> 5, c = (s & 31) * 4;
    float4 v = *(const float4*)(Qg + (size_t)(q0 + r) * DH + c);
    QsT[(c + 0) * 68 + r] = v.x; QsT[(c + 1) * 68 + r] = v.y;
    QsT[(c + 2) * 68 + r] = v.z; QsT[(c + 3) * 68 + r] = v.w;
  }

  float m_run[4], l_run[4], o[4][8];
#pragma unroll
  for (int r = 0; r < 4; r++) { m_run[r] = -1e30f; l_run[r] = 0.f; }
#pragma unroll
  for (int r = 0; r < 4; r++)
#pragma unroll
    for (int j = 0; j < 8; j++) o[r][j] = 0.f;

  const float scale = 0.08838834764831845f;  // 1/sqrt(128)

  for (int kt = 0; kt <= qt; kt++) {
    const int k0 = kt * 64;
    __syncthreads();  // prior PV reads of Vs/PsT done before overwrite
#pragma unroll
    for (int i = 0; i < 8; i++) {
      int s = tid + i * 256;
      int r = s >> 5, c = (s & 31) * 4;
      float4 v = *(const float4*)(Kg + (size_t)(k0 + r) * DH + c);
      KsT[(c + 0) * 68 + r] = v.x; KsT[(c + 1) * 68 + r] = v.y;
      KsT[(c + 2) * 68 + r] = v.z; KsT[(c + 3) * 68 + r] = v.w;
      float4 w = *(const float4*)(Vg + (size_t)(k0 + r) * DH + c);
      *(float4*)(&Vs[r * 132 + c]) = w;
    }
    __syncthreads();

    // S = Q @ K^T (per-thread 4x4)
    float s4[4][4];
#pragma unroll
    for (int r = 0; r < 4; r++)
#pragma unroll
      for (int c = 0; c < 4; c++) s4[r][c] = 0.f;
#pragma unroll 4
    for (int d = 0; d < 128; d++) {
      float4 qv = *(float4*)(&QsT[d * 68 + ty * 4]);
      float4 kv = *(float4*)(&KsT[d * 68 + tx * 4]);
      float qa[4] = {qv.x, qv.y, qv.z, qv.w};
      float ka[4] = {kv.x, kv.y, kv.z, kv.w};
#pragma unroll
      for (int r = 0; r < 4; r++)
#pragma unroll
        for (int c = 0; c < 4; c++) s4[r][c] += qa[r] * ka[c];
    }
#pragma unroll
    for (int r = 0; r < 4; r++)
#pragma unroll
      for (int c = 0; c < 4; c++) s4[r][c] *= scale;

    if (kt == qt) {  // only diagonal tile needs the causal mask
#pragma unroll
      for (int r = 0; r < 4; r++)
#pragma unroll
        for (int c = 0; c < 4; c++)
          if (tx * 4 + c > ty * 4 + r) s4[r][c] = -1e30f;
    }

    // Online softmax: row reductions across the 16-lane tx group
    float mt[4];
#pragma unroll
    for (int r = 0; r < 4; r++) {
      float m0 = fmaxf(fmaxf(s4[r][0], s4[r][1]), fmaxf(s4[r][2], s4[r][3]));
#pragma unroll
      for (int off = 8; off > 0; off >>= 1)
        m0 = fmaxf(m0, __shfl_xor_sync(0xffffffffu, m0, off));
      mt[r] = m0;
    }
    float corr[4], rowsum[4];
#pragma unroll
    for (int r = 0; r < 4; r++) {
      float mnew = fmaxf(m_run[r], mt[r]);
      corr[r] = __expf(m_run[r] - mnew);
      m_run[r] = mnew;
      float rs = 0.f;
#pragma unroll
      for (int c = 0; c < 4; c++) {
        float p = __expf(s4[r][c] - mnew);
        rs += p;
        PsT[(tx * 4 + c) * 68 + ty * 4 + r] = p;  // kk-major for PV
      }
#pragma unroll
      for (int off = 8; off > 0; off >>= 1)
        rs += __shfl_xor_sync(0xffffffffu, rs, off);
      rowsum[r] = rs;
    }
#pragma unroll
    for (int r = 0; r < 4; r++) {
      l_run[r] = l_run[r] * corr[r] + rowsum[r];
#pragma unroll
      for (int j = 0; j < 8; j++) o[r][j] *= corr[r];
    }
    __syncthreads();  // PsT writes visible to all

    // O += P @ V
#pragma unroll 2
    for (int kk = 0; kk < 64; kk++) {
      float4 pv = *(float4*)(&PsT[kk * 68 + ty * 4]);
      float4 v0 = *(float4*)(&Vs[kk * 132 + tx * 8]);
      float4 v1 = *(float4*)(&Vs[kk * 132 + tx * 8 + 4]);
      float pa[4] = {pv.x, pv.y, pv.z, pv.w};
      float va[8] = {v0.x, v0.y, v0.z, v0.w, v1.x, v1.y, v1.z, v1.w};
#pragma unroll
      for (int r = 0; r < 4; r++)
#pragma unroll
        for (int j = 0; j < 8; j++) o[r][j] += pa[r] * va[j];
    }
  }

  const int b = bh >> 4, h = bh & 15;
#pragma unroll
  for (int r = 0; r < 4; r++) {
    float inv = 1.f / l_run[r];
    int row = q0 + ty * 4 + r;
    float* dst = g_ctx + (size_t)(b * SEQ + row) * DM + h * DH + tx * 8;
#pragma unroll
    for (int j = 0; j < 8; j++) dst[j] = o[r][j] * inv;
  }
}

// ---------------------------------------------------------------------------
// GEMM 2: out = ctx @ W_out + b_out.  ctx: [4096,2048], W_out: [2048,2048]
// ---------------------------------------------------------------------------
__global__ __launch_bounds__(256, 2) void gemm_out_kernel(
    const float* __restrict__ Bw, const float* __restrict__ bias,
    float* __restrict__ out) {
  const int K = DM, N = DM;
  const float* A = g_ctx;
  __shared__ float As[16][132];
  __shared__ float Bs[16][132];
  const int bm = blockIdx.y * 128, bn = blockIdx.x * 128;
  const int tid = threadIdx.x;
  const int tx = tid & 15, ty = tid >> 4;
  float acc[8][8];
#pragma unroll
  for (int i = 0; i < 8; i++)
#pragma unroll
    for (int j = 0; j < 8; j++) acc[i][j] = 0.f;

  for (int k0 = 0; k0 < K; k0 += 16) {
#pragma unroll
    for (int i = 0; i < 2; i++) {
      int s = tid + i * 256;
      int row = s >> 2, c4 = (s & 3) * 4;
      float4 v = *(const float4*)(A + (size_t)(bm + row) * K + k0 + c4);
      As[c4 + 0][row] = v.x; As[c4 + 1][row] = v.y;
      As[c4 + 2][row] = v.z; As[c4 + 3][row] = v.w;
    }
#pragma unroll
    for (int i = 0; i < 2; i++) {
      int s = tid + i * 256;
      int row = s >> 5, c4 = (s & 31) * 4;
      *(float4*)(&Bs[row][c4]) =
          *(const float4*)(Bw + (size_t)(k0 + row) * N + bn + c4);
    }
    __syncthreads();
#pragma unroll
    for (int kk = 0; kk < 16; kk++) {
      float a[8], b[8];
      *(float4*)(a)     = *(float4*)(&As[kk][ty * 8]);
      *(float4*)(a + 4) = *(float4*)(&As[kk][ty * 8 + 4]);
      *(float4*)(b)     = *(float4*)(&Bs[kk][tx * 8]);
      *(float4*)(b + 4) = *(float4*)(&Bs[kk][tx * 8 + 4]);
#pragma unroll
      for (int i = 0; i < 8; i++)
#pragma unroll
        for (int j = 0; j < 8; j++) acc[i][j] += a[i] * b[j];
    }
    __syncthreads();
  }
#pragma unroll
  for (int i = 0; i < 8; i++) {
    int m = bm + ty * 8 + i;
#pragma unroll
    for (int j = 0; j < 8; j++) {
      int n = bn + tx * 8 + j;
      out[(size_t)m * N + n] = acc[i][j] + bias[n];
    }
  }
}

// ---------------------------------------------------------------------------
extern "C" void kernel_launch(void* const* d_in, const int* in_sizes, int n_in,
                              void* d_out, int out_size) {
  const float* x    = (const float*)d_in[0];
  const float* Wqkv = (const float*)d_in[1];
  const float* bqkv = (const float*)d_in[2];
  const float* Wout = (const float*)d_in[3];
  const float* bout = (const float*)d_in[4];
  float* out = (float*)d_out;

  // 120832 B dynamic smem for flash (idempotent; legal during capture)
  cudaFuncSetAttribute(flash_kernel,
                       cudaFuncAttributeMaxDynamicSharedMemorySize, 120832);

  gemm_qkv_kernel<<<dim3(48, 32), 256>>>(x, Wqkv, bqkv);
  flash_kernel<<<dim3(32, 32), 256, 120832>>>();
  gemm_out_kernel<<<dim3(16, 32), 256>>>(Wout, bout, out);
}

// round 5
// speedup vs baseline: 1.8809x; 1.8809x over previous
#include <cuda_runtime.h>
#include <math.h>

#define NB 2
#define NH 16
#define SEQ 2048
#define DH 128
#define DM 2048          // NH*DH
#define MTOK (NB*SEQ)    // 4096

// Scratch (static device allocations — allowed; no cudaMalloc anywhere)
__device__ float g_qkvh[(size_t)3 * NB * NH * SEQ * DH];  // [3][B][H][S][D]
__device__ float g_ctx[(size_t)MTOK * DM];                // [B*S][DM]

// ---------------------------------------------------------------------------
// TF32 helpers
// ---------------------------------------------------------------------------
__device__ __forceinline__ unsigned f2tf(float x) {
  unsigned r;
  asm("cvt.rna.tf32.f32 %0, %1;" : "=r"(r) : "f"(x));
  return r;
}

__device__ __forceinline__ void mma_tf32(float& c0, float& c1, float& c2,
                                         float& c3, unsigned a0, unsigned a1,
                                         unsigned a2, unsigned a3, unsigned b0,
                                         unsigned b1) {
  asm volatile(
      "mma.sync.aligned.m16n8k8.row.col.f32.tf32.tf32.f32 "
      "{%0,%1,%2,%3},{%4,%5,%6,%7},{%8,%9},{%0,%1,%2,%3};\n"
      : "+f"(c0), "+f"(c1), "+f"(c2), "+f"(c3)
      : "r"(a0), "r"(a1), "r"(a2), "r"(a3), "r"(b0), "r"(b1));
}

__device__ __forceinline__ unsigned smem_u32(const void* p) {
  return (unsigned)__cvta_generic_to_shared(p);
}

#define CP16(dst_u32, gptr) \
  asm volatile("cp.async.cg.shared.global [%0], [%1], 16;\n" ::"r"(dst_u32), \
               "l"(gptr))

// ---------------------------------------------------------------------------
// TF32 tensor-core GEMM: C[M,N] = A[M,K] @ B[K,N] + bias
// CTA 128x128x32, 8 warps (2m x 4n), warp tile 64x32, mma m16n8k8.
// As[128][36] (stride%32==4 -> conflict-free A frags)
// Bs[32][136] (stride%32==8 -> conflict-free B frags)
// QKV_SCATTER: epilogue writes head-major g_qkvh instead of row-major C.
// A_FROM_CTX: resolve A = g_ctx inside device code (a __device__ array must
//             NOT be passed as a kernel argument from host code).
// ---------------------------------------------------------------------------
#define SA 36
#define SB 136
#define AS_ELEMS (128 * SA)
#define BS_ELEMS (32 * SB)
#define GEMM_SMEM ((2 * AS_ELEMS + 2 * BS_ELEMS) * 4)  // 71680 B

template <int N, bool QKV_SCATTER, bool A_FROM_CTX>
__global__ __launch_bounds__(256, 2) void gemm_mma_kernel(
    const float* __restrict__ Ain, const float* __restrict__ Bw,
    const float* __restrict__ bias, float* __restrict__ Cout) {
  extern __shared__ float sm[];
  const float* A = A_FROM_CTX ? g_ctx : Ain;  // device-side symbol resolution
  float* AsBase = sm;                  // [2][128][36]
  float* BsBase = sm + 2 * AS_ELEMS;   // [2][32][136]
  const int K = DM;
  const int bm = blockIdx.y * 128, bn = blockIdx.x * 128;
  const int tid = threadIdx.x;
  const int warp = tid >> 5, lane = tid & 31;
  const int wm = (warp & 1) * 64;   // warp m offset in CTA tile
  const int wn = (warp >> 1) * 32;  // warp n offset

  float acc[4][4][4];
#pragma unroll
  for (int mf = 0; mf < 4; mf++)
#pragma unroll
    for (int nf = 0; nf < 4; nf++)
#pragma unroll
      for (int i = 0; i < 4; i++) acc[mf][nf][i] = 0.f;

  // loader index precompute
  const int la_m = tid >> 3, la_k = (tid & 7) << 2;   // A: 8x16B units per row
  const int lb_k = tid >> 5, lb_n = (tid & 31) << 2;  // B: 32 units per row

  auto load_tile = [&](int k0, int buf) {
    float* as = AsBase + buf * AS_ELEMS;
    float* bs = BsBase + buf * BS_ELEMS;
#pragma unroll
    for (int u = 0; u < 4; u++) {
      int m = la_m + u * 32;  // 256 thr / 8 units = 32 rows per pass
      CP16(smem_u32(as + m * SA + la_k),
           A + (size_t)(bm + m) * K + k0 + la_k);
    }
#pragma unroll
    for (int u = 0; u < 4; u++) {
      int kb = lb_k + u * 8;  // 256 thr / 32 units = 8 rows per pass
      CP16(smem_u32(bs + kb * SB + lb_n),
           Bw + (size_t)(k0 + kb) * N + bn + lb_n);
    }
    asm volatile("cp.async.commit_group;\n");
  };

  load_tile(0, 0);

  const int lr = lane >> 2, lc = lane & 3;

  for (int t = 0; t < K / 32; t++) {
    if (t + 1 < K / 32) {
      load_tile((t + 1) * 32, (t + 1) & 1);
      asm volatile("cp.async.wait_group 1;\n");
    } else {
      asm volatile("cp.async.wait_group 0;\n");
    }
    __syncthreads();

    const float* as = AsBase + (t & 1) * AS_ELEMS;
    const float* bs = BsBase + (t & 1) * BS_ELEMS;

#pragma unroll
    for (int ks = 0; ks < 4; ks++) {
      const int kb = ks * 8;
      unsigned a[4][4];
#pragma unroll
      for (int mf = 0; mf < 4; mf++) {
        const float* ap = as + (wm + mf * 16 + lr) * SA + kb + lc;
        a[mf][0] = f2tf(ap[0]);
        a[mf][1] = f2tf(ap[8 * SA]);
        a[mf][2] = f2tf(ap[4]);
        a[mf][3] = f2tf(ap[8 * SA + 4]);
      }
      unsigned b[4][2];
#pragma unroll
      for (int nf = 0; nf < 4; nf++) {
        const float* bp = bs + (kb + lc) * SB + wn + nf * 8 + lr;
        b[nf][0] = f2tf(bp[0]);
        b[nf][1] = f2tf(bp[4 * SB]);
      }
#pragma unroll
      for (int mf = 0; mf < 4; mf++)
#pragma unroll
        for (int nf = 0; nf < 4; nf++)
          mma_tf32(acc[mf][nf][0], acc[mf][nf][1], acc[mf][nf][2],
                   acc[mf][nf][3], a[mf][0], a[mf][1], a[mf][2], a[mf][3],
                   b[nf][0], b[nf][1]);
    }
    __syncthreads();
  }

  // Epilogue
#pragma unroll
  for (int mf = 0; mf < 4; mf++) {
#pragma unroll
    for (int nf = 0; nf < 4; nf++) {
      int r0 = bm + wm + mf * 16 + lr;
      int c0 = bn + wn + nf * 8 + 2 * lc;
      float bia0 = bias[c0], bia1 = bias[c0 + 1];
      float v00 = acc[mf][nf][0] + bia0, v01 = acc[mf][nf][1] + bia1;
      float v10 = acc[mf][nf][2] + bia0, v11 = acc[mf][nf][3] + bia1;
      if (QKV_SCATTER) {
        int which = c0 >> 11, rr = c0 & 2047;
        int h = rr >> 7, d = rr & 127;
#pragma unroll
        for (int rv = 0; rv < 2; rv++) {
          int m = r0 + rv * 8;
          int b = m >> 11, sidx = m & 2047;
          float* dst = g_qkvh +
                       (size_t)(((which * NB + b) * NH + h) * SEQ + sidx) * DH +
                       d;
          float2 v = rv ? make_float2(v10, v11) : make_float2(v00, v01);
          *(float2*)dst = v;
        }
      } else {
        *(float2*)(Cout + (size_t)r0 * N + c0) = make_float2(v00, v01);
        *(float2*)(Cout + (size_t)(r0 + 8) * N + c0) = make_float2(v10, v11);
      }
    }
  }
}

// ---------------------------------------------------------------------------
// Flash attention (fp32, unchanged from R1): causal, online softmax.
// Grid: (32 q-tiles, 32 B*H), 256 threads, 120832 B dynamic smem.
// ---------------------------------------------------------------------------
__global__ __launch_bounds__(256) void flash_kernel() {
  extern __shared__ float sm[];
  float* QsT = sm;                 // [128][68] (d-major)
  float* KsT = sm + 128 * 68;      // [128][68]
  float* Vs  = sm + 2 * 128 * 68;  // [64][132]
  float* PsT = Vs + 64 * 132;      // [64 kk][68 rows]
  const int bh = blockIdx.y;
  const int qt = blockIdx.x;
  const float* Qg = g_qkvh + (size_t)bh * SEQ * DH;
  const float* Kg = g_qkvh + (size_t)(32 + bh) * SEQ * DH;
  const float* Vg = g_qkvh + (size_t)(64 + bh) * SEQ * DH;
  const int q0 = qt * 64;
  const int tid = threadIdx.x, tx = tid & 15, ty = tid >> 4;

#pragma unroll
  for (int i = 0; i < 8; i++) {
    int s = tid + i * 256;
    int r = s >> 5, c = (s & 31) * 4;
    float4 v = *(const float4*)(Qg + (size_t)(q0 + r) * DH + c);
    QsT[(c + 0) * 68 + r] = v.x; QsT[(c + 1) * 68 + r] = v.y;
    QsT[(c + 2) * 68 + r] = v.z; QsT[(c + 3) * 68 + r] = v.w;
  }

  float m_run[4], l_run[4], o[4][8];
#pragma unroll
  for (int r = 0; r < 4; r++) { m_run[r] = -1e30f; l_run[r] = 0.f; }
#pragma unroll
  for (int r = 0; r < 4; r++)
#pragma unroll
    for (int j = 0; j < 8; j++) o[r][j] = 0.f;

  const float scale = 0.08838834764831845f;  // 1/sqrt(128)

  for (int kt = 0; kt <= qt; kt++) {
    const int k0 = kt * 64;
    __syncthreads();
#pragma unroll
    for (int i = 0; i < 8; i++) {
      int s = tid + i * 256;
      int r = s >> 5, c = (s & 31) * 4;
      float4 v = *(const float4*)(Kg + (size_t)(k0 + r) * DH + c);
      KsT[(c + 0) * 68 + r] = v.x; KsT[(c + 1) * 68 + r] = v.y;
      KsT[(c + 2) * 68 + r] = v.z; KsT[(c + 3) * 68 + r] = v.w;
      float4 w = *(const float4*)(Vg + (size_t)(k0 + r) * DH + c);
      *(float4*)(&Vs[r * 132 + c]) = w;
    }
    __syncthreads();

    float s4[4][4];
#pragma unroll
    for (int r = 0; r < 4; r++)
#pragma unroll
      for (int c = 0; c < 4; c++) s4[r][c] = 0.f;
#pragma unroll 4
    for (int d = 0; d < 128; d++) {
      float4 qv = *(float4*)(&QsT[d * 68 + ty * 4]);
      float4 kv = *(float4*)(&KsT[d * 68 + tx * 4]);
      float qa[4] = {qv.x, qv.y, qv.z, qv.w};
      float ka[4] = {kv.x, kv.y, kv.z, kv.w};
#pragma unroll
      for (int r = 0; r < 4; r++)
#pragma unroll
        for (int c = 0; c < 4; c++) s4[r][c] += qa[r] * ka[c];
    }
#pragma unroll
    for (int r = 0; r < 4; r++)
#pragma unroll
      for (int c = 0; c < 4; c++) s4[r][c] *= scale;

    if (kt == qt) {
#pragma unroll
      for (int r = 0; r < 4; r++)
#pragma unroll
        for (int c = 0; c < 4; c++)
          if (tx * 4 + c > ty * 4 + r) s4[r][c] = -1e30f;
    }

    float mt[4];
#pragma unroll
    for (int r = 0; r < 4; r++) {
      float m0 = fmaxf(fmaxf(s4[r][0], s4[r][1]), fmaxf(s4[r][2], s4[r][3]));
#pragma unroll
      for (int off = 8; off > 0; off >>= 1)
        m0 = fmaxf(m0, __shfl_xor_sync(0xffffffffu, m0, off));
      mt[r] = m0;
    }
    float corr[4], rowsum[4];
#pragma unroll
    for (int r = 0; r < 4; r++) {
      float mnew = fmaxf(m_run[r], mt[r]);
      corr[r] = __expf(m_run[r] - mnew);
      m_run[r] = mnew;
      float rs = 0.f;
#pragma unroll
      for (int c = 0; c < 4; c++) {
        float p = __expf(s4[r][c] - mnew);
        rs += p;
        PsT[(tx * 4 + c) * 68 + ty * 4 + r] = p;
      }
#pragma unroll
      for (int off = 8; off > 0; off >>= 1)
        rs += __shfl_xor_sync(0xffffffffu, rs, off);
      rowsum[r] = rs;
    }
#pragma unroll
    for (int r = 0; r < 4; r++) {
      l_run[r] = l_run[r] * corr[r] + rowsum[r];
#pragma unroll
      for (int j = 0; j < 8; j++) o[r][j] *= corr[r];
    }
    __syncthreads();

#pragma unroll 2
    for (int kk = 0; kk < 64; kk++) {
      float4 pv = *(float4*)(&PsT[kk * 68 + ty * 4]);
      float4 v0 = *(float4*)(&Vs[kk * 132 + tx * 8]);
      float4 v1 = *(float4*)(&Vs[kk * 132 + tx * 8 + 4]);
      float pa[4] = {pv.x, pv.y, pv.z, pv.w};
      float va[8] = {v0.x, v0.y, v0.z, v0.w, v1.x, v1.y, v1.z, v1.w};
#pragma unroll
      for (int r = 0; r < 4; r++)
#pragma unroll
        for (int j = 0; j < 8; j++) o[r][j] += pa[r] * va[j];
    }
  }

  const int b = bh >> 4, h = bh & 15;
#pragma unroll
  for (int r = 0; r < 4; r++) {
    float inv = 1.f / l_run[r];
    int row = q0 + ty * 4 + r;
    float* dst = g_ctx + (size_t)(b * SEQ + row) * DM + h * DH + tx * 8;
#pragma unroll
    for (int j = 0; j < 8; j++) dst[j] = o[r][j] * inv;
  }
}

// ---------------------------------------------------------------------------
extern "C" void kernel_launch(void* const* d_in, const int* in_sizes, int n_in,
                              void* d_out, int out_size) {
  const float* x    = (const float*)d_in[0];
  const float* Wqkv = (const float*)d_in[1];
  const float* bqkv = (const float*)d_in[2];
  const float* Wout = (const float*)d_in[3];
  const float* bout = (const float*)d_in[4];
  float* out = (float*)d_out;

  cudaFuncSetAttribute(gemm_mma_kernel<3 * DM, true, false>,
                       cudaFuncAttributeMaxDynamicSharedMemorySize, GEMM_SMEM);
  cudaFuncSetAttribute(gemm_mma_kernel<DM, false, true>,
                       cudaFuncAttributeMaxDynamicSharedMemorySize, GEMM_SMEM);
  cudaFuncSetAttribute(flash_kernel,
                       cudaFuncAttributeMaxDynamicSharedMemorySize, 120832);

  gemm_mma_kernel<3 * DM, true, false>
      <<<dim3(48, 32), 256, GEMM_SMEM>>>(x, Wqkv, bqkv, nullptr);
  flash_kernel<<<dim3(32, 32), 256, 120832>>>();
  gemm_mma_kernel<DM, false, true>
      <<<dim3(16, 32), 256, GEMM_SMEM>>>(nullptr, Wout, bout, out);
}

// round 7
// speedup vs baseline: 3.7438x; 1.9904x over previous
#include <cuda_runtime.h>
#include <math.h>

#define NB 2
#define NH 16
#define SEQ 2048
#define DH 128
#define DM 2048          // NH*DH
#define MTOK (NB*SEQ)    // 4096

// Scratch (static device allocations — allowed; no cudaMalloc anywhere)
__device__ float g_qkvh[(size_t)3 * NB * NH * SEQ * DH];  // [3][B][H][S][D] (tf32-rounded)
__device__ float g_ctx[(size_t)MTOK * DM];                // [B*S][DM]

// ---------------------------------------------------------------------------
// TF32 helpers
// ---------------------------------------------------------------------------
__device__ __forceinline__ unsigned f2tf(float x) {
  unsigned r;
  asm("cvt.rna.tf32.f32 %0, %1;" : "=r"(r) : "f"(x));
  return r;
}

__device__ __forceinline__ void mma_tf32(float& c0, float& c1, float& c2,
                                         float& c3, unsigned a0, unsigned a1,
                                         unsigned a2, unsigned a3, unsigned b0,
                                         unsigned b1) {
  asm volatile(
      "mma.sync.aligned.m16n8k8.row.col.f32.tf32.tf32.f32 "
      "{%0,%1,%2,%3},{%4,%5,%6,%7},{%8,%9},{%0,%1,%2,%3};\n"
      : "+f"(c0), "+f"(c1), "+f"(c2), "+f"(c3)
      : "r"(a0), "r"(a1), "r"(a2), "r"(a3), "r"(b0), "r"(b1));
}

__device__ __forceinline__ unsigned smem_u32(const void* p) {
  return (unsigned)__cvta_generic_to_shared(p);
}

#define CP16(dst_u32, gptr) \
  asm volatile("cp.async.cg.shared.global [%0], [%1], 16;\n" ::"r"(dst_u32), \
               "l"(gptr))

// ---------------------------------------------------------------------------
// TF32 tensor-core GEMM (unchanged from R5; QKV scatter pre-rounds to tf32).
// ---------------------------------------------------------------------------
#define SA 36
#define SB 136
#define AS_ELEMS (128 * SA)
#define BS_ELEMS (32 * SB)
#define GEMM_SMEM ((2 * AS_ELEMS + 2 * BS_ELEMS) * 4)  // 71680 B

template <int N, bool QKV_SCATTER, bool A_FROM_CTX>
__global__ __launch_bounds__(256, 2) void gemm_mma_kernel(
    const float* __restrict__ Ain, const float* __restrict__ Bw,
    const float* __restrict__ bias, float* __restrict__ Cout) {
  extern __shared__ float sm[];
  const float* A = A_FROM_CTX ? g_ctx : Ain;  // device-side symbol resolution
  float* AsBase = sm;                  // [2][128][36]
  float* BsBase = sm + 2 * AS_ELEMS;   // [2][32][136]
  const int K = DM;
  const int bm = blockIdx.y * 128, bn = blockIdx.x * 128;
  const int tid = threadIdx.x;
  const int warp = tid >> 5, lane = tid & 31;
  const int wm = (warp & 1) * 64;
  const int wn = (warp >> 1) * 32;

  float acc[4][4][4];
#pragma unroll
  for (int mf = 0; mf < 4; mf++)
#pragma unroll
    for (int nf = 0; nf < 4; nf++)
#pragma unroll
      for (int i = 0; i < 4; i++) acc[mf][nf][i] = 0.f;

  const int la_m = tid >> 3, la_k = (tid & 7) << 2;
  const int lb_k = tid >> 5, lb_n = (tid & 31) << 2;

  auto load_tile = [&](int k0, int buf) {
    float* as = AsBase + buf * AS_ELEMS;
    float* bs = BsBase + buf * BS_ELEMS;
#pragma unroll
    for (int u = 0; u < 4; u++) {
      int m = la_m + u * 32;
      CP16(smem_u32(as + m * SA + la_k),
           A + (size_t)(bm + m) * K + k0 + la_k);
    }
#pragma unroll
    for (int u = 0; u < 4; u++) {
      int kb = lb_k + u * 8;
      CP16(smem_u32(bs + kb * SB + lb_n),
           Bw + (size_t)(k0 + kb) * N + bn + lb_n);
    }
    asm volatile("cp.async.commit_group;\n");
  };

  load_tile(0, 0);

  const int lr = lane >> 2, lc = lane & 3;

  for (int t = 0; t < K / 32; t++) {
    if (t + 1 < K / 32) {
      load_tile((t + 1) * 32, (t + 1) & 1);
      asm volatile("cp.async.wait_group 1;\n");
    } else {
      asm volatile("cp.async.wait_group 0;\n");
    }
    __syncthreads();

    const float* as = AsBase + (t & 1) * AS_ELEMS;
    const float* bs = BsBase + (t & 1) * BS_ELEMS;

#pragma unroll
    for (int ks = 0; ks < 4; ks++) {
      const int kb = ks * 8;
      unsigned a[4][4];
#pragma unroll
      for (int mf = 0; mf < 4; mf++) {
        const float* ap = as + (wm + mf * 16 + lr) * SA + kb + lc;
        a[mf][0] = f2tf(ap[0]);
        a[mf][1] = f2tf(ap[8 * SA]);
        a[mf][2] = f2tf(ap[4]);
        a[mf][3] = f2tf(ap[8 * SA + 4]);
      }
      unsigned b[4][2];
#pragma unroll
      for (int nf = 0; nf < 4; nf++) {
        const float* bp = bs + (kb + lc) * SB + wn + nf * 8 + lr;
        b[nf][0] = f2tf(bp[0]);
        b[nf][1] = f2tf(bp[4 * SB]);
      }
#pragma unroll
      for (int mf = 0; mf < 4; mf++)
#pragma unroll
        for (int nf = 0; nf < 4; nf++)
          mma_tf32(acc[mf][nf][0], acc[mf][nf][1], acc[mf][nf][2],
                   acc[mf][nf][3], a[mf][0], a[mf][1], a[mf][2], a[mf][3],
                   b[nf][0], b[nf][1]);
    }
    __syncthreads();
  }

#pragma unroll
  for (int mf = 0; mf < 4; mf++) {
#pragma unroll
    for (int nf = 0; nf < 4; nf++) {
      int r0 = bm + wm + mf * 16 + lr;
      int c0 = bn + wn + nf * 8 + 2 * lc;
      float bia0 = bias[c0], bia1 = bias[c0 + 1];
      float v00 = acc[mf][nf][0] + bia0, v01 = acc[mf][nf][1] + bia1;
      float v10 = acc[mf][nf][2] + bia0, v11 = acc[mf][nf][3] + bia1;
      if (QKV_SCATTER) {
        // pre-round to tf32: flash consumes raw bits, no cvt needed there
        v00 = __uint_as_float(f2tf(v00));
        v01 = __uint_as_float(f2tf(v01));
        v10 = __uint_as_float(f2tf(v10));
        v11 = __uint_as_float(f2tf(v11));
        int which = c0 >> 11, rr = c0 & 2047;
        int h = rr >> 7, d = rr & 127;
#pragma unroll
        for (int rv = 0; rv < 2; rv++) {
          int m = r0 + rv * 8;
          int b = m >> 11, sidx = m & 2047;
          float* dst = g_qkvh +
                       (size_t)(((which * NB + b) * NH + h) * SEQ + sidx) * DH +
                       d;
          float2 v = rv ? make_float2(v10, v11) : make_float2(v00, v01);
          *(float2*)dst = v;
        }
      } else {
        *(float2*)(Cout + (size_t)r0 * N + c0) = make_float2(v00, v01);
        *(float2*)(Cout + (size_t)(r0 + 8) * N + c0) = make_float2(v10, v11);
      }
    }
  }
}

// ---------------------------------------------------------------------------
// TF32 flash attention. CTA: 128 q-rows, 64 k-cols/iter, 8 warps.
// Each warp owns 16 q-rows -> online softmax is warp-private.
// Qs[128][132] (A-frags, stride%32==4: conflict-free)
// Ks[64][132]  (B-frags read as K[n=seq][k=d]: stride%32==4 conflict-free)
// Vs[64][136]  (B-frags read as V[k=kk][n=d]: stride%32==8 conflict-free)
// Ps per-warp [16][68] (P re-staged as A-frags for PV)
// Q/K/V pre-rounded to tf32 by the QKV GEMM -> raw bit feed, no cvt here.
// ---------------------------------------------------------------------------
#define QS_S 132
#define KS_S 132
#define VS_S 136
#define PS_S 68
#define FLASH_SMEM \
  ((128 * QS_S + 64 * KS_S + 64 * VS_S + 8 * 16 * PS_S) * 4)  // 171008 B

__global__ __launch_bounds__(256, 1) void flash_mma_kernel() {
  extern __shared__ float sm[];
  float* Qs = sm;                        // [128][132]
  float* Ks = Qs + 128 * QS_S;           // [64][132]
  float* Vs = Ks + 64 * KS_S;            // [64][136]
  float* Ps = Vs + 64 * VS_S;            // [8][16][68]

  const int bh = blockIdx.y;
  const int qt = gridDim.x - 1 - blockIdx.x;  // longest CTAs first
  const int q0 = qt * 128;
  const float* Qg = g_qkvh + (size_t)bh * SEQ * DH + (size_t)q0 * DH;
  const float* Kg = g_qkvh + (size_t)(32 + bh) * SEQ * DH;
  const float* Vg = g_qkvh + (size_t)(64 + bh) * SEQ * DH;
  const int tid = threadIdx.x;
  const int warp = tid >> 5, lane = tid & 31;
  const int lr = lane >> 2, lc = lane & 3;
  const int wm = warp * 16;
  float* Pw = Ps + warp * (16 * PS_S);

  // Q tile: 128 rows x 32 16B-chunks = 4096 chunks / 256 thr = 16 each
#pragma unroll
  for (int u = 0; u < 16; u++) {
    int s = tid + u * 256;
    int r = s >> 5, c = (s & 31) * 4;
    CP16(smem_u32(Qs + r * QS_S + c), Qg + (size_t)r * DH + c);
  }
  asm volatile("cp.async.commit_group;\n");

  float o[16][4];
#pragma unroll
  for (int nf = 0; nf < 16; nf++)
#pragma unroll
    for (int i = 0; i < 4; i++) o[nf][i] = 0.f;
  float m0 = -1e30f, m1 = -1e30f, l0 = 0.f, l1 = 0.f;

  const float scale = 0.08838834764831845f;  // 1/sqrt(128)
  const int nkt = 2 * qt + 2;

  for (int kt = 0; kt < nkt; kt++) {
    const int k0 = kt * 64;
    __syncthreads();  // prior iter's Ks/Vs reads complete
    // K,V tiles: 64 rows x 32 chunks each = 2048 chunks -> 8 per thread each
#pragma unroll
    for (int u = 0; u < 8; u++) {
      int s = tid + u * 256;
      int r = s >> 5, c = (s & 31) * 4;
      CP16(smem_u32(Ks + r * KS_S + c), Kg + (size_t)(k0 + r) * DH + c);
      CP16(smem_u32(Vs + r * VS_S + c), Vg + (size_t)(k0 + r) * DH + c);
    }
    asm volatile("cp.async.commit_group;\ncp.async.wait_group 0;\n");
    __syncthreads();

    // ---- S = Q @ K^T  (warp rows wm..wm+15, cols 0..63) ----
    // B-frag: need B[k=d][n=seq] = K[seq=nf*8+lr][d=kb+lc] (Ks is [seq][d])
    float sc[8][4];
#pragma unroll
    for (int nf = 0; nf < 8; nf++)
#pragma unroll
      for (int i = 0; i < 4; i++) sc[nf][i] = 0.f;
#pragma unroll
    for (int ks = 0; ks < 16; ks++) {
      const int kb = ks * 8;
      unsigned a0 = __float_as_uint(Qs[(wm + lr) * QS_S + kb + lc]);
      unsigned a1 = __float_as_uint(Qs[(wm + lr + 8) * QS_S + kb + lc]);
      unsigned a2 = __float_as_uint(Qs[(wm + lr) * QS_S + kb + lc + 4]);
      unsigned a3 = __float_as_uint(Qs[(wm + lr + 8) * QS_S + kb + lc + 4]);
#pragma unroll
      for (int nf = 0; nf < 8; nf++) {
        unsigned b0 = __float_as_uint(Ks[(nf * 8 + lr) * KS_S + kb + lc]);
        unsigned b1 = __float_as_uint(Ks[(nf * 8 + lr) * KS_S + kb + lc + 4]);
        mma_tf32(sc[nf][0], sc[nf][1], sc[nf][2], sc[nf][3], a0, a1, a2, a3,
                 b0, b1);
      }
    }
#pragma unroll
    for (int nf = 0; nf < 8; nf++)
#pragma unroll
      for (int i = 0; i < 4; i++) sc[nf][i] *= scale;

    // ---- causal mask (only tiles crossing this warp's diagonal) ----
    const int r0g = q0 + wm + lr, r1g = r0g + 8;
    if (k0 + 63 > r0g) {
#pragma unroll
      for (int nf = 0; nf < 8; nf++) {
        int cg = k0 + nf * 8 + 2 * lc;
        if (cg > r0g) sc[nf][0] = -1e30f;
        if (cg + 1 > r0g) sc[nf][1] = -1e30f;
        if (cg > r1g) sc[nf][2] = -1e30f;
        if (cg + 1 > r1g) sc[nf][3] = -1e30f;
      }
    }

    // ---- online softmax (warp-private rows) ----
    float mx0 = sc[0][0], mx1 = sc[0][2];
#pragma unroll
    for (int nf = 0; nf < 8; nf++) {
      mx0 = fmaxf(mx0, fmaxf(sc[nf][0], sc[nf][1]));
      mx1 = fmaxf(mx1, fmaxf(sc[nf][2], sc[nf][3]));
    }
    mx0 = fmaxf(mx0, __shfl_xor_sync(0xffffffffu, mx0, 1));
    mx0 = fmaxf(mx0, __shfl_xor_sync(0xffffffffu, mx0, 2));
    mx1 = fmaxf(mx1, __shfl_xor_sync(0xffffffffu, mx1, 1));
    mx1 = fmaxf(mx1, __shfl_xor_sync(0xffffffffu, mx1, 2));
    float mn0 = fmaxf(m0, mx0), mn1 = fmaxf(m1, mx1);
    float cr0 = __expf(m0 - mn0), cr1 = __expf(m1 - mn1);
    m0 = mn0; m1 = mn1;
    float rs0 = 0.f, rs1 = 0.f;
#pragma unroll
    for (int nf = 0; nf < 8; nf++) {
      float p00 = __expf(sc[nf][0] - mn0);
      float p01 = __expf(sc[nf][1] - mn0);
      float p10 = __expf(sc[nf][2] - mn1);
      float p11 = __expf(sc[nf][3] - mn1);
      rs0 += p00 + p01;
      rs1 += p10 + p11;
      *(float2*)(Pw + lr * PS_S + nf * 8 + 2 * lc) = make_float2(p00, p01);
      *(float2*)(Pw + (lr + 8) * PS_S + nf * 8 + 2 * lc) =
          make_float2(p10, p11);
    }
    rs0 += __shfl_xor_sync(0xffffffffu, rs0, 1);
    rs0 += __shfl_xor_sync(0xffffffffu, rs0, 2);
    rs1 += __shfl_xor_sync(0xffffffffu, rs1, 1);
    rs1 += __shfl_xor_sync(0xffffffffu, rs1, 2);
    l0 = l0 * cr0 + rs0;
    l1 = l1 * cr1 + rs1;
#pragma unroll
    for (int nf = 0; nf < 16; nf++) {
      o[nf][0] *= cr0; o[nf][1] *= cr0;
      o[nf][2] *= cr1; o[nf][3] *= cr1;
    }
    __syncwarp();  // Ps is warp-private: warp-level visibility suffices

    // ---- O += P @ V  (V is [kk][d] = [K][N]: same orientation as GEMM Bw) ----
#pragma unroll
    for (int ks = 0; ks < 8; ks++) {
      const int kb = ks * 8;
      unsigned a0 = __float_as_uint(Pw[lr * PS_S + kb + lc]);
      unsigned a1 = __float_as_uint(Pw[(lr + 8) * PS_S + kb + lc]);
      unsigned a2 = __float_as_uint(Pw[lr * PS_S + kb + lc + 4]);
      unsigned a3 = __float_as_uint(Pw[(lr + 8) * PS_S + kb + lc + 4]);
#pragma unroll
      for (int nf = 0; nf < 16; nf++) {
        unsigned b0 = __float_as_uint(Vs[(kb + lc) * VS_S + nf * 8 + lr]);
        unsigned b1 = __float_as_uint(Vs[(kb + lc + 4) * VS_S + nf * 8 + lr]);
        mma_tf32(o[nf][0], o[nf][1], o[nf][2], o[nf][3], a0, a1, a2, a3, b0,
                 b1);
      }
    }
    __syncwarp();  // PV reads of Pw done before next iter overwrites
  }

  // ---- epilogue: normalize, write ctx [B*S][DM] ----
  const int b = bh >> 4, h = bh & 15;
  const float inv0 = 1.f / l0, inv1 = 1.f / l1;
  const int r0g = q0 + wm + lr, r1g = r0g + 8;
  float* base0 = g_ctx + (size_t)(b * SEQ + r0g) * DM + h * DH;
  float* base1 = g_ctx + (size_t)(b * SEQ + r1g) * DM + h * DH;
#pragma unroll
  for (int nf = 0; nf < 16; nf++) {
    *(float2*)(base0 + nf * 8 + 2 * lc) =
        make_float2(o[nf][0] * inv0, o[nf][1] * inv0);
    *(float2*)(base1 + nf * 8 + 2 * lc) =
        make_float2(o[nf][2] * inv1, o[nf][3] * inv1);
  }
}

// ---------------------------------------------------------------------------
extern "C" void kernel_launch(void* const* d_in, const int* in_sizes, int n_in,
                              void* d_out, int out_size) {
  const float* x    = (const float*)d_in[0];
  const float* Wqkv = (const float*)d_in[1];
  const float* bqkv = (const float*)d_in[2];
  const float* Wout = (const float*)d_in[3];
  const float* bout = (const float*)d_in[4];
  float* out = (float*)d_out;

  cudaFuncSetAttribute(gemm_mma_kernel<3 * DM, true, false>,
                       cudaFuncAttributeMaxDynamicSharedMemorySize, GEMM_SMEM);
  cudaFuncSetAttribute(gemm_mma_kernel<DM, false, true>,
                       cudaFuncAttributeMaxDynamicSharedMemorySize, GEMM_SMEM);
  cudaFuncSetAttribute(flash_mma_kernel,
                       cudaFuncAttributeMaxDynamicSharedMemorySize, FLASH_SMEM);

  gemm_mma_kernel<3 * DM, true, false>
      <<<dim3(48, 32), 256, GEMM_SMEM>>>(x, Wqkv, bqkv, nullptr);
  flash_mma_kernel<<<dim3(16, 32), 256, FLASH_SMEM>>>();
  gemm_mma_kernel<DM, false, true>
      <<<dim3(16, 32), 256, GEMM_SMEM>>>(nullptr, Wout, bout, out);
}

// round 8
// speedup vs baseline: 3.8047x; 1.0163x over previous
#include <cuda_runtime.h>
#include <math.h>

#define NB 2
#define NH 16
#define SEQ 2048
#define DH 128
#define DM 2048          // NH*DH
#define MTOK (NB*SEQ)    // 4096

// Scratch (static device allocations — allowed; no cudaMalloc anywhere)
__device__ float g_qkvh[(size_t)3 * NB * NH * SEQ * DH];  // [3][B][H][S][D] (tf32-rounded)
__device__ float g_ctx[(size_t)MTOK * DM];   // [B*S][DM] (tf32-rounded)
__device__ float g_xr[(size_t)MTOK * DM];    // x rounded to tf32
__device__ float g_wqkv[(size_t)DM * 3 * DM];// W_qkv rounded to tf32
__device__ float g_wout[(size_t)DM * DM];    // W_out rounded to tf32

// ---------------------------------------------------------------------------
// TF32 helpers
// ---------------------------------------------------------------------------
__device__ __forceinline__ unsigned f2tf(float x) {
  unsigned r;
  asm("cvt.rna.tf32.f32 %0, %1;" : "=r"(r) : "f"(x));
  return r;
}

__device__ __forceinline__ void mma_tf32(float& c0, float& c1, float& c2,
                                         float& c3, unsigned a0, unsigned a1,
                                         unsigned a2, unsigned a3, unsigned b0,
                                         unsigned b1) {
  asm volatile(
      "mma.sync.aligned.m16n8k8.row.col.f32.tf32.tf32.f32 "
      "{%0,%1,%2,%3},{%4,%5,%6,%7},{%8,%9},{%0,%1,%2,%3};\n"
      : "+f"(c0), "+f"(c1), "+f"(c2), "+f"(c3)
      : "r"(a0), "r"(a1), "r"(a2), "r"(a3), "r"(b0), "r"(b1));
}

__device__ __forceinline__ unsigned smem_u32(const void* p) {
  return (unsigned)__cvta_generic_to_shared(p);
}

#define CP16(dst_u32, gptr) \
  asm volatile("cp.async.cg.shared.global [%0], [%1], 16;\n" ::"r"(dst_u32), \
               "l"(gptr))

// ---------------------------------------------------------------------------
// Prepass: round fp32 arrays to tf32-valued fp32 (grid-stride, float4)
// which: 0 -> g_xr, 1 -> g_wqkv, 2 -> g_wout
// ---------------------------------------------------------------------------
__global__ void round_tf32_kernel(const float4* __restrict__ src, int n4,
                                  int which) {
  float4* dst = which == 0   ? (float4*)g_xr
                : which == 1 ? (float4*)g_wqkv
                             : (float4*)g_wout;
  for (int i = blockIdx.x * blockDim.x + threadIdx.x; i < n4;
       i += gridDim.x * blockDim.x) {
    float4 v = src[i];
    v.x = __uint_as_float(f2tf(v.x));
    v.y = __uint_as_float(f2tf(v.y));
    v.z = __uint_as_float(f2tf(v.z));
    v.w = __uint_as_float(f2tf(v.w));
    dst[i] = v;
  }
}

// ---------------------------------------------------------------------------
// TF32 tensor-core GEMM: inputs already tf32-rounded -> raw-bit fragment feed
// (zero cvt in mainloop). CTA 128x128x32, 8 warps, warp tile 64x32.
// ASRC: 1=g_xr, 2=g_ctx   BSRC: 1=g_wqkv, 2=g_wout
// ---------------------------------------------------------------------------
#define SA 36
#define SB 136
#define AS_ELEMS (128 * SA)
#define BS_ELEMS (32 * SB)
#define GEMM_SMEM ((2 * AS_ELEMS + 2 * BS_ELEMS) * 4)  // 71680 B

template <int N, int ASRC, int BSRC, bool QKV_SCATTER>
__global__ __launch_bounds__(256, 2) void gemm_mma_kernel(
    const float* __restrict__ bias, float* __restrict__ Cout) {
  extern __shared__ float sm[];
  const float* A = (ASRC == 1) ? g_xr : g_ctx;
  const float* Bw = (BSRC == 1) ? g_wqkv : g_wout;
  float* AsBase = sm;                  // [2][128][36]
  float* BsBase = sm + 2 * AS_ELEMS;   // [2][32][136]
  const int K = DM;
  const int bm = blockIdx.y * 128, bn = blockIdx.x * 128;
  const int tid = threadIdx.x;
  const int warp = tid >> 5, lane = tid & 31;
  const int wm = (warp & 1) * 64;
  const int wn = (warp >> 1) * 32;

  float acc[4][4][4];
#pragma unroll
  for (int mf = 0; mf < 4; mf++)
#pragma unroll
    for (int nf = 0; nf < 4; nf++)
#pragma unroll
      for (int i = 0; i < 4; i++) acc[mf][nf][i] = 0.f;

  const int la_m = tid >> 3, la_k = (tid & 7) << 2;
  const int lb_k = tid >> 5, lb_n = (tid & 31) << 2;

  auto load_tile = [&](int k0, int buf) {
    float* as = AsBase + buf * AS_ELEMS;
    float* bs = BsBase + buf * BS_ELEMS;
#pragma unroll
    for (int u = 0; u < 4; u++) {
      int m = la_m + u * 32;
      CP16(smem_u32(as + m * SA + la_k),
           A + (size_t)(bm + m) * K + k0 + la_k);
    }
#pragma unroll
    for (int u = 0; u < 4; u++) {
      int kb = lb_k + u * 8;
      CP16(smem_u32(bs + kb * SB + lb_n),
           Bw + (size_t)(k0 + kb) * N + bn + lb_n);
    }
    asm volatile("cp.async.commit_group;\n");
  };

  load_tile(0, 0);

  const int lr = lane >> 2, lc = lane & 3;

  for (int t = 0; t < K / 32; t++) {
    if (t + 1 < K / 32) {
      load_tile((t + 1) * 32, (t + 1) & 1);
      asm volatile("cp.async.wait_group 1;\n");
    } else {
      asm volatile("cp.async.wait_group 0;\n");
    }
    __syncthreads();

    const float* as = AsBase + (t & 1) * AS_ELEMS;
    const float* bs = BsBase + (t & 1) * BS_ELEMS;

#pragma unroll
    for (int ks = 0; ks < 4; ks++) {
      const int kb = ks * 8;
      unsigned a[4][4];
#pragma unroll
      for (int mf = 0; mf < 4; mf++) {
        const float* ap = as + (wm + mf * 16 + lr) * SA + kb + lc;
        a[mf][0] = __float_as_uint(ap[0]);
        a[mf][1] = __float_as_uint(ap[8 * SA]);
        a[mf][2] = __float_as_uint(ap[4]);
        a[mf][3] = __float_as_uint(ap[8 * SA + 4]);
      }
      unsigned b[4][2];
#pragma unroll
      for (int nf = 0; nf < 4; nf++) {
        const float* bp = bs + (kb + lc) * SB + wn + nf * 8 + lr;
        b[nf][0] = __float_as_uint(bp[0]);
        b[nf][1] = __float_as_uint(bp[4 * SB]);
      }
#pragma unroll
      for (int mf = 0; mf < 4; mf++)
#pragma unroll
        for (int nf = 0; nf < 4; nf++)
          mma_tf32(acc[mf][nf][0], acc[mf][nf][1], acc[mf][nf][2],
                   acc[mf][nf][3], a[mf][0], a[mf][1], a[mf][2], a[mf][3],
                   b[nf][0], b[nf][1]);
    }
    __syncthreads();
  }

#pragma unroll
  for (int mf = 0; mf < 4; mf++) {
#pragma unroll
    for (int nf = 0; nf < 4; nf++) {
      int r0 = bm + wm + mf * 16 + lr;
      int c0 = bn + wn + nf * 8 + 2 * lc;
      float bia0 = bias[c0], bia1 = bias[c0 + 1];
      float v00 = acc[mf][nf][0] + bia0, v01 = acc[mf][nf][1] + bia1;
      float v10 = acc[mf][nf][2] + bia0, v11 = acc[mf][nf][3] + bia1;
      if (QKV_SCATTER) {
        // pre-round to tf32: flash consumes raw bits, no cvt needed there
        v00 = __uint_as_float(f2tf(v00));
        v01 = __uint_as_float(f2tf(v01));
        v10 = __uint_as_float(f2tf(v10));
        v11 = __uint_as_float(f2tf(v11));
        int which = c0 >> 11, rr = c0 & 2047;
        int h = rr >> 7, d = rr & 127;
#pragma unroll
        for (int rv = 0; rv < 2; rv++) {
          int m = r0 + rv * 8;
          int b = m >> 11, sidx = m & 2047;
          float* dst = g_qkvh +
                       (size_t)(((which * NB + b) * NH + h) * SEQ + sidx) * DH +
                       d;
          float2 v = rv ? make_float2(v10, v11) : make_float2(v00, v01);
          *(float2*)dst = v;
        }
      } else {
        *(float2*)(Cout + (size_t)r0 * N + c0) = make_float2(v00, v01);
        *(float2*)(Cout + (size_t)(r0 + 8) * N + c0) = make_float2(v10, v11);
      }
    }
  }
}

// ---------------------------------------------------------------------------
// TF32 flash attention (R7, plus: ctx stored tf32-rounded for the out GEMM).
// CTA: 128 q-rows, 64 k-cols/iter, 8 warps; warp-private online softmax.
// ---------------------------------------------------------------------------
#define QS_S 132
#define KS_S 132
#define VS_S 136
#define PS_S 68
#define FLASH_SMEM \
  ((128 * QS_S + 64 * KS_S + 64 * VS_S + 8 * 16 * PS_S) * 4)  // 171008 B

__global__ __launch_bounds__(256, 1) void flash_mma_kernel() {
  extern __shared__ float sm[];
  float* Qs = sm;                        // [128][132]
  float* Ks = Qs + 128 * QS_S;           // [64][132]
  float* Vs = Ks + 64 * KS_S;            // [64][136]
  float* Ps = Vs + 64 * VS_S;            // [8][16][68]

  const int bh = blockIdx.y;
  const int qt = gridDim.x - 1 - blockIdx.x;  // longest CTAs first
  const int q0 = qt * 128;
  const float* Qg = g_qkvh + (size_t)bh * SEQ * DH + (size_t)q0 * DH;
  const float* Kg = g_qkvh + (size_t)(32 + bh) * SEQ * DH;
  const float* Vg = g_qkvh + (size_t)(64 + bh) * SEQ * DH;
  const int tid = threadIdx.x;
  const int warp = tid >> 5, lane = tid & 31;
  const int lr = lane >> 2, lc = lane & 3;
  const int wm = warp * 16;
  float* Pw = Ps + warp * (16 * PS_S);

#pragma unroll
  for (int u = 0; u < 16; u++) {
    int s = tid + u * 256;
    int r = s >> 5, c = (s & 31) * 4;
    CP16(smem_u32(Qs + r * QS_S + c), Qg + (size_t)r * DH + c);
  }
  asm volatile("cp.async.commit_group;\n");

  float o[16][4];
#pragma unroll
  for (int nf = 0; nf < 16; nf++)
#pragma unroll
    for (int i = 0; i < 4; i++) o[nf][i] = 0.f;
  float m0 = -1e30f, m1 = -1e30f, l0 = 0.f, l1 = 0.f;

  const float scale = 0.08838834764831845f;  // 1/sqrt(128)
  const int nkt = 2 * qt + 2;

  for (int kt = 0; kt < nkt; kt++) {
    const int k0 = kt * 64;
    __syncthreads();
#pragma unroll
    for (int u = 0; u < 8; u++) {
      int s = tid + u * 256;
      int r = s >> 5, c = (s & 31) * 4;
      CP16(smem_u32(Ks + r * KS_S + c), Kg + (size_t)(k0 + r) * DH + c);
      CP16(smem_u32(Vs + r * VS_S + c), Vg + (size_t)(k0 + r) * DH + c);
    }
    asm volatile("cp.async.commit_group;\ncp.async.wait_group 0;\n");
    __syncthreads();

    // ---- S = Q @ K^T ----
    float sc[8][4];
#pragma unroll
    for (int nf = 0; nf < 8; nf++)
#pragma unroll
      for (int i = 0; i < 4; i++) sc[nf][i] = 0.f;
#pragma unroll
    for (int ks = 0; ks < 16; ks++) {
      const int kb = ks * 8;
      unsigned a0 = __float_as_uint(Qs[(wm + lr) * QS_S + kb + lc]);
      unsigned a1 = __float_as_uint(Qs[(wm + lr + 8) * QS_S + kb + lc]);
      unsigned a2 = __float_as_uint(Qs[(wm + lr) * QS_S + kb + lc + 4]);
      unsigned a3 = __float_as_uint(Qs[(wm + lr + 8) * QS_S + kb + lc + 4]);
#pragma unroll
      for (int nf = 0; nf < 8; nf++) {
        unsigned b0 = __float_as_uint(Ks[(nf * 8 + lr) * KS_S + kb + lc]);
        unsigned b1 = __float_as_uint(Ks[(nf * 8 + lr) * KS_S + kb + lc + 4]);
        mma_tf32(sc[nf][0], sc[nf][1], sc[nf][2], sc[nf][3], a0, a1, a2, a3,
                 b0, b1);
      }
    }
#pragma unroll
    for (int nf = 0; nf < 8; nf++)
#pragma unroll
      for (int i = 0; i < 4; i++) sc[nf][i] *= scale;

    // ---- causal mask ----
    const int r0g = q0 + wm + lr, r1g = r0g + 8;
    if (k0 + 63 > r0g) {
#pragma unroll
      for (int nf = 0; nf < 8; nf++) {
        int cg = k0 + nf * 8 + 2 * lc;
        if (cg > r0g) sc[nf][0] = -1e30f;
        if (cg + 1 > r0g) sc[nf][1] = -1e30f;
        if (cg > r1g) sc[nf][2] = -1e30f;
        if (cg + 1 > r1g) sc[nf][3] = -1e30f;
      }
    }

    // ---- online softmax (warp-private rows) ----
    float mx0 = sc[0][0], mx1 = sc[0][2];
#pragma unroll
    for (int nf = 0; nf < 8; nf++) {
      mx0 = fmaxf(mx0, fmaxf(sc[nf][0], sc[nf][1]));
      mx1 = fmaxf(mx1, fmaxf(sc[nf][2], sc[nf][3]));
    }
    mx0 = fmaxf(mx0, __shfl_xor_sync(0xffffffffu, mx0, 1));
    mx0 = fmaxf(mx0, __shfl_xor_sync(0xffffffffu, mx0, 2));
    mx1 = fmaxf(mx1, __shfl_xor_sync(0xffffffffu, mx1, 1));
    mx1 = fmaxf(mx1, __shfl_xor_sync(0xffffffffu, mx1, 2));
    float mn0 = fmaxf(m0, mx0), mn1 = fmaxf(m1, mx1);
    float cr0 = __expf(m0 - mn0), cr1 = __expf(m1 - mn1);
    m0 = mn0; m1 = mn1;
    float rs0 = 0.f, rs1 = 0.f;
#pragma unroll
    for (int nf = 0; nf < 8; nf++) {
      float p00 = __expf(sc[nf][0] - mn0);
      float p01 = __expf(sc[nf][1] - mn0);
      float p10 = __expf(sc[nf][2] - mn1);
      float p11 = __expf(sc[nf][3] - mn1);
      rs0 += p00 + p01;
      rs1 += p10 + p11;
      *(float2*)(Pw + lr * PS_S + nf * 8 + 2 * lc) = make_float2(p00, p01);
      *(float2*)(Pw + (lr + 8) * PS_S + nf * 8 + 2 * lc) =
          make_float2(p10, p11);
    }
    rs0 += __shfl_xor_sync(0xffffffffu, rs0, 1);
    rs0 += __shfl_xor_sync(0xffffffffu, rs0, 2);
    rs1 += __shfl_xor_sync(0xffffffffu, rs1, 1);
    rs1 += __shfl_xor_sync(0xffffffffu, rs1, 2);
    l0 = l0 * cr0 + rs0;
    l1 = l1 * cr1 + rs1;
#pragma unroll
    for (int nf = 0; nf < 16; nf++) {
      o[nf][0] *= cr0; o[nf][1] *= cr0;
      o[nf][2] *= cr1; o[nf][3] *= cr1;
    }
    __syncwarp();

    // ---- O += P @ V ----
#pragma unroll
    for (int ks = 0; ks < 8; ks++) {
      const int kb = ks * 8;
      unsigned a0 = __float_as_uint(Pw[lr * PS_S + kb + lc]);
      unsigned a1 = __float_as_uint(Pw[(lr + 8) * PS_S + kb + lc]);
      unsigned a2 = __float_as_uint(Pw[lr * PS_S + kb + lc + 4]);
      unsigned a3 = __float_as_uint(Pw[(lr + 8) * PS_S + kb + lc + 4]);
#pragma unroll
      for (int nf = 0; nf < 16; nf++) {
        unsigned b0 = __float_as_uint(Vs[(kb + lc) * VS_S + nf * 8 + lr]);
        unsigned b1 = __float_as_uint(Vs[(kb + lc + 4) * VS_S + nf * 8 + lr]);
        mma_tf32(o[nf][0], o[nf][1], o[nf][2], o[nf][3], a0, a1, a2, a3, b0,
                 b1);
      }
    }
    __syncwarp();
  }

  // ---- epilogue: normalize, round to tf32, write ctx [B*S][DM] ----
  const int b = bh >> 4, h = bh & 15;
  const float inv0 = 1.f / l0, inv1 = 1.f / l1;
  const int r0g = q0 + wm + lr, r1g = r0g + 8;
  float* base0 = g_ctx + (size_t)(b * SEQ + r0g) * DM + h * DH;
  float* base1 = g_ctx + (size_t)(b * SEQ + r1g) * DM + h * DH;
#pragma unroll
  for (int nf = 0; nf < 16; nf++) {
    *(float2*)(base0 + nf * 8 + 2 * lc) =
        make_float2(__uint_as_float(f2tf(o[nf][0] * inv0)),
                    __uint_as_float(f2tf(o[nf][1] * inv0)));
    *(float2*)(base1 + nf * 8 + 2 * lc) =
        make_float2(__uint_as_float(f2tf(o[nf][2] * inv1)),
                    __uint_as_float(f2tf(o[nf][3] * inv1)));
  }
}

// ---------------------------------------------------------------------------
extern "C" void kernel_launch(void* const* d_in, const int* in_sizes, int n_in,
                              void* d_out, int out_size) {
  const float* x    = (const float*)d_in[0];
  const float* Wqkv = (const float*)d_in[1];
  const float* bqkv = (const float*)d_in[2];
  const float* Wout = (const float*)d_in[3];
  const float* bout = (const float*)d_in[4];
  float* out = (float*)d_out;

  cudaFuncSetAttribute(gemm_mma_kernel<3 * DM, 1, 1, true>,
                       cudaFuncAttributeMaxDynamicSharedMemorySize, GEMM_SMEM);
  cudaFuncSetAttribute(gemm_mma_kernel<DM, 2, 2, false>,
                       cudaFuncAttributeMaxDynamicSharedMemorySize, GEMM_SMEM);
  cudaFuncSetAttribute(flash_mma_kernel,
                       cudaFuncAttributeMaxDynamicSharedMemorySize, FLASH_SMEM);

  // Prepass: tf32-round x, W_qkv, W_out (grid-stride float4)
  round_tf32_kernel<<<2048, 256>>>((const float4*)x, MTOK * DM / 4, 0);
  round_tf32_kernel<<<2048, 256>>>((const float4*)Wqkv, DM * 3 * DM / 4, 1);
  round_tf32_kernel<<<2048, 256>>>((const float4*)Wout, DM * DM / 4, 2);

  gemm_mma_kernel<3 * DM, 1, 1, true>
      <<<dim3(48, 32), 256, GEMM_SMEM>>>(bqkv, nullptr);
  flash_mma_kernel<<<dim3(16, 32), 256, FLASH_SMEM>>>();
  gemm_mma_kernel<DM, 2, 2, false>
      <<<dim3(16, 32), 256, GEMM_SMEM>>>(bout, out);
}

// round 12
// speedup vs baseline: 5.4518x; 1.4329x over previous
#include <cuda_runtime.h>
#include <cuda_fp16.h>
#include <cstdint>
#include <math.h>

#define NB 2
#define NH 16
#define SEQ 2048
#define DH 128
#define DM 2048          // NH*DH
#define MTOK (NB*SEQ)    // 4096

// Scratch (static device allocations — allowed; no cudaMalloc anywhere)
__device__ float  g_qkvh[(size_t)3 * NB * NH * SEQ * DH];  // [3][B][H][S][D] tf32
__device__ __half g_xh[(size_t)MTOK * DM];      // x fp16            [M][K]
__device__ __half g_wqkvh[(size_t)3 * DM * DM]; // W_qkv^T fp16      [N=6144][K]
__device__ __half g_wouth[(size_t)DM * DM];     // W_out^T fp16      [N=2048][K]
__device__ __half g_ctxh[(size_t)MTOK * DM];    // ctx fp16          [M][K]

// ---------------------------------------------------------------------------
// helpers
// ---------------------------------------------------------------------------
__device__ __forceinline__ unsigned f2tf(float x) {
  unsigned r;
  asm("cvt.rna.tf32.f32 %0, %1;" : "=r"(r) : "f"(x));
  return r;
}
__device__ __forceinline__ void mma_tf32(float& c0, float& c1, float& c2,
                                         float& c3, unsigned a0, unsigned a1,
                                         unsigned a2, unsigned a3, unsigned b0,
                                         unsigned b1) {
  asm volatile(
      "mma.sync.aligned.m16n8k8.row.col.f32.tf32.tf32.f32 "
      "{%0,%1,%2,%3},{%4,%5,%6,%7},{%8,%9},{%0,%1,%2,%3};\n"
      : "+f"(c0), "+f"(c1), "+f"(c2), "+f"(c3)
      : "r"(a0), "r"(a1), "r"(a2), "r"(a3), "r"(b0), "r"(b1));
}
// fp16 mma m16n8k16: A row-major [16x16], B col-major [8 cols x 16 k], C f32
__device__ __forceinline__ void mma_f16(float& c0, float& c1, float& c2,
                                        float& c3, unsigned a0, unsigned a1,
                                        unsigned a2, unsigned a3, unsigned b0,
                                        unsigned b1) {
  asm volatile(
      "mma.sync.aligned.m16n8k16.row.col.f32.f16.f16.f32 "
      "{%0,%1,%2,%3},{%4,%5,%6,%7},{%8,%9},{%0,%1,%2,%3};\n"
      : "+f"(c0), "+f"(c1), "+f"(c2), "+f"(c3)
      : "r"(a0), "r"(a1), "r"(a2), "r"(a3), "r"(b0), "r"(b1));
}
__device__ __forceinline__ unsigned smem_u32(const void* p) {
  return (unsigned)__cvta_generic_to_shared(p);
}
#define CP16(dst_u32, gptr) \
  asm volatile("cp.async.cg.shared.global [%0], [%1], 16;\n" ::"r"(dst_u32), \
               "l"(gptr))

// ---------------------------------------------------------------------------
// Prepass 1: x (fp32) -> g_xh (fp16), layout unchanged
// ---------------------------------------------------------------------------
__global__ void x_to_h_kernel(const float4* __restrict__ src, int n4) {
  __half2* dst = (__half2*)g_xh;
  for (int i = blockIdx.x * blockDim.x + threadIdx.x; i < n4;
       i += gridDim.x * blockDim.x) {
    float4 v = src[i];
    dst[2 * i] = __floats2half2_rn(v.x, v.y);
    dst[2 * i + 1] = __floats2half2_rn(v.z, v.w);
  }
}

// ---------------------------------------------------------------------------
// Prepass 2: W [K=2048][NCOLS] fp32 -> W^T [NCOLS][2048] fp16
// ---------------------------------------------------------------------------
template <int NCOLS, int WHICH>
__global__ void transpose_h_kernel(const float* __restrict__ src) {
  __half* dst = (WHICH == 1) ? g_wqkvh : g_wouth;
  __shared__ float tile[32][33];
  const int n0 = blockIdx.x * 32, k0 = blockIdx.y * 32;
  const int tx = threadIdx.x, ty = threadIdx.y;  // 32 x 8
#pragma unroll
  for (int i = 0; i < 32; i += 8)
    tile[ty + i][tx] = src[(size_t)(k0 + ty + i) * NCOLS + n0 + tx];
  __syncthreads();
#pragma unroll
  for (int i = 0; i < 32; i += 8)
    dst[(size_t)(n0 + ty + i) * DM + k0 + tx] =
        __float2half_rn(tile[tx][ty + i]);
}

// ---------------------------------------------------------------------------
// FP16 tensor-core GEMM: C[M,N] = A[M,2048](h) @ B^T (B stored [N][2048](h))
// CTA 128x128, K-tile 64, 8 warps (2m x 4n), warp tile 64x32, mma m16n8k16.
// Smem rows: 72 halves (36 words; 36%32==4 -> every 32-bit frag load
// conflict-free: banks 4*lr+lc). Double-buffered cp.async.
// QKV_SCATTER: head-major tf32-rounded fp32 scatter into g_qkvh.
// ---------------------------------------------------------------------------
#define SH 72                    // halves per smem row
#define TILE_H (128 * SH)        // halves per tile (A or B)
#define GEMM_SMEM (2 * 2 * TILE_H * 2)  // 2 buf x (A+B) x 2B = 73728 B

template <int N, bool QKV_SCATTER, bool A_FROM_CTX>
__global__ __launch_bounds__(256, 2) void gemm_h_kernel(
    const float* __restrict__ bias, float* __restrict__ Cout) {
  extern __shared__ __half smh[];
  const __half* A = A_FROM_CTX ? g_ctxh : g_xh;
  const __half* Bw = QKV_SCATTER ? g_wqkvh : g_wouth;
  __half* AsBase = smh;                 // [2][128][72]
  __half* BsBase = smh + 2 * TILE_H;    // [2][128][72]
  const int K = DM;
  const int bm = blockIdx.y * 128, bn = blockIdx.x * 128;
  const int tid = threadIdx.x;
  const int warp = tid >> 5, lane = tid & 31;
  const int wm = (warp & 1) * 64;   // warp m offset
  const int wn = (warp >> 1) * 32;  // warp n offset

  float acc[4][4][4];
#pragma unroll
  for (int mf = 0; mf < 4; mf++)
#pragma unroll
    for (int nf = 0; nf < 4; nf++)
#pragma unroll
      for (int i = 0; i < 4; i++) acc[mf][nf][i] = 0.f;

  auto load_tile = [&](int k0, int buf) {
    __half* as = AsBase + buf * TILE_H;
    __half* bs = BsBase + buf * TILE_H;
    // 128 rows x 8 chunks (16B = 8 halves) = 1024 chunks each for A and B
#pragma unroll
    for (int i = 0; i < 4; i++) {
      int cid = tid + i * 256;
      int row = cid >> 3, u = cid & 7;
      CP16(smem_u32(as + row * SH + u * 8),
           A + (size_t)(bm + row) * K + k0 + u * 8);
    }
#pragma unroll
    for (int i = 0; i < 4; i++) {
      int cid = tid + i * 256;
      int row = cid >> 3, u = cid & 7;
      CP16(smem_u32(bs + row * SH + u * 8),
           Bw + (size_t)(bn + row) * K + k0 + u * 8);
    }
    asm volatile("cp.async.commit_group;\n");
  };

  load_tile(0, 0);

  const int lr = lane >> 2, lc = lane & 3;

  for (int t = 0; t < K / 64; t++) {
    if (t + 1 < K / 64) {
      load_tile((t + 1) * 64, (t + 1) & 1);
      asm volatile("cp.async.wait_group 1;\n");
    } else {
      asm volatile("cp.async.wait_group 0;\n");
    }
    __syncthreads();

    const __half* as = AsBase + (t & 1) * TILE_H;
    const __half* bs = BsBase + (t & 1) * TILE_H;

#pragma unroll
    for (int ks = 0; ks < 4; ks++) {       // 4 x k=16 per tile
      const int kh = ks * 16;              // half offset within row
      unsigned a[4][4];
#pragma unroll
      for (int mf = 0; mf < 4; mf++) {
        const __half* ap = as + (wm + mf * 16 + lr) * SH + kh + 2 * lc;
        a[mf][0] = *(const unsigned*)(ap);            // row lr,   k 2lc..2lc+1
        a[mf][1] = *(const unsigned*)(ap + 8 * SH);   // row lr+8
        a[mf][2] = *(const unsigned*)(ap + 8);        // row lr,   k +8
        a[mf][3] = *(const unsigned*)(ap + 8 * SH + 8);
      }
      unsigned b[4][2];
#pragma unroll
      for (int nf = 0; nf < 4; nf++) {
        const __half* bp = bs + (wn + nf * 8 + lr) * SH + kh + 2 * lc;
        b[nf][0] = *(const unsigned*)(bp);      // col lr, k 2lc..2lc+1
        b[nf][1] = *(const unsigned*)(bp + 8);  // col lr, k +8
      }
#pragma unroll
      for (int mf = 0; mf < 4; mf++)
#pragma unroll
        for (int nf = 0; nf < 4; nf++)
          mma_f16(acc[mf][nf][0], acc[mf][nf][1], acc[mf][nf][2],
                  acc[mf][nf][3], a[mf][0], a[mf][1], a[mf][2], a[mf][3],
                  b[nf][0], b[nf][1]);
    }
    __syncthreads();
  }

  // Epilogue (C frag layout identical to tf32 path)
#pragma unroll
  for (int mf = 0; mf < 4; mf++) {
#pragma unroll
    for (int nf = 0; nf < 4; nf++) {
      int r0 = bm + wm + mf * 16 + lr;
      int c0 = bn + wn + nf * 8 + 2 * lc;
      float bia0 = bias[c0], bia1 = bias[c0 + 1];
      float v00 = acc[mf][nf][0] + bia0, v01 = acc[mf][nf][1] + bia1;
      float v10 = acc[mf][nf][2] + bia0, v11 = acc[mf][nf][3] + bia1;
      if (QKV_SCATTER) {
        // tf32-round: the tf32 flash kernel raw-feeds these bits
        v00 = __uint_as_float(f2tf(v00));
        v01 = __uint_as_float(f2tf(v01));
        v10 = __uint_as_float(f2tf(v10));
        v11 = __uint_as_float(f2tf(v11));
        int which = c0 >> 11, rr = c0 & 2047;
        int h = rr >> 7, d = rr & 127;
#pragma unroll
        for (int rv = 0; rv < 2; rv++) {
          int m = r0 + rv * 8;
          int b = m >> 11, sidx = m & 2047;
          float* dst = g_qkvh +
                       (size_t)(((which * NB + b) * NH + h) * SEQ + sidx) * DH +
                       d;
          float2 v = rv ? make_float2(v10, v11) : make_float2(v00, v01);
          *(float2*)dst = v;
        }
      } else {
        *(float2*)(Cout + (size_t)r0 * N + c0) = make_float2(v00, v01);
        *(float2*)(Cout + (size_t)(r0 + 8) * N + c0) = make_float2(v10, v11);
      }
    }
  }
}

// ---------------------------------------------------------------------------
// TF32 flash attention (passing since R7). Epilogue now writes ctx as fp16
// for the fp16 out-GEMM.
// ---------------------------------------------------------------------------
#define QS_S 132
#define KS_S 132
#define VS_S 136
#define PS_S 68
#define FLASH_SMEM \
  ((128 * QS_S + 64 * KS_S + 64 * VS_S + 8 * 16 * PS_S) * 4)  // 171008 B

__global__ __launch_bounds__(256, 1) void flash_mma_kernel() {
  extern __shared__ float sm[];
  float* Qs = sm;
  float* Ks = Qs + 128 * QS_S;
  float* Vs = Ks + 64 * KS_S;
  float* Ps = Vs + 64 * VS_S;

  const int bh = blockIdx.y;
  const int qt = gridDim.x - 1 - blockIdx.x;
  const int q0 = qt * 128;
  const float* Qg = g_qkvh + (size_t)bh * SEQ * DH + (size_t)q0 * DH;
  const float* Kg = g_qkvh + (size_t)(32 + bh) * SEQ * DH;
  const float* Vg = g_qkvh + (size_t)(64 + bh) * SEQ * DH;
  const int tid = threadIdx.x;
  const int warp = tid >> 5, lane = tid & 31;
  const int lr = lane >> 2, lc = lane & 3;
  const int wm = warp * 16;
  float* Pw = Ps + warp * (16 * PS_S);

#pragma unroll
  for (int u = 0; u < 16; u++) {
    int s = tid + u * 256;
    int r = s >> 5, c = (s & 31) * 4;
    CP16(smem_u32(Qs + r * QS_S + c), Qg + (size_t)r * DH + c);
  }
  asm volatile("cp.async.commit_group;\n");

  float o[16][4];
#pragma unroll
  for (int nf = 0; nf < 16; nf++)
#pragma unroll
    for (int i = 0; i < 4; i++) o[nf][i] = 0.f;
  float m0 = -1e30f, m1 = -1e30f, l0 = 0.f, l1 = 0.f;

  const float scale = 0.08838834764831845f;
  const int nkt = 2 * qt + 2;

  for (int kt = 0; kt < nkt; kt++) {
    const int k0 = kt * 64;
    __syncthreads();
#pragma unroll
    for (int u = 0; u < 8; u++) {
      int s = tid + u * 256;
      int r = s >> 5, c = (s & 31) * 4;
      CP16(smem_u32(Ks + r * KS_S + c), Kg + (size_t)(k0 + r) * DH + c);
      CP16(smem_u32(Vs + r * VS_S + c), Vg + (size_t)(k0 + r) * DH + c);
    }
    asm volatile("cp.async.commit_group;\ncp.async.wait_group 0;\n");
    __syncthreads();

    float sc[8][4];
#pragma unroll
    for (int nf = 0; nf < 8; nf++)
#pragma unroll
      for (int i = 0; i < 4; i++) sc[nf][i] = 0.f;
#pragma unroll
    for (int ks = 0; ks < 16; ks++) {
      const int kb = ks * 8;
      unsigned a0 = __float_as_uint(Qs[(wm + lr) * QS_S + kb + lc]);
      unsigned a1 = __float_as_uint(Qs[(wm + lr + 8) * QS_S + kb + lc]);
      unsigned a2 = __float_as_uint(Qs[(wm + lr) * QS_S + kb + lc + 4]);
      unsigned a3 = __float_as_uint(Qs[(wm + lr + 8) * QS_S + kb + lc + 4]);
#pragma unroll
      for (int nf = 0; nf < 8; nf++) {
        unsigned b0 = __float_as_uint(Ks[(nf * 8 + lr) * KS_S + kb + lc]);
        unsigned b1 = __float_as_uint(Ks[(nf * 8 + lr) * KS_S + kb + lc + 4]);
        mma_tf32(sc[nf][0], sc[nf][1], sc[nf][2], sc[nf][3], a0, a1, a2, a3,
                 b0, b1);
      }
    }
#pragma unroll
    for (int nf = 0; nf < 8; nf++)
#pragma unroll
      for (int i = 0; i < 4; i++) sc[nf][i] *= scale;

    const int r0g = q0 + wm + lr, r1g = r0g + 8;
    if (k0 + 63 > r0g) {
#pragma unroll
      for (int nf = 0; nf < 8; nf++) {
        int cg = k0 + nf * 8 + 2 * lc;
        if (cg > r0g) sc[nf][0] = -1e30f;
        if (cg + 1 > r0g) sc[nf][1] = -1e30f;
        if (cg > r1g) sc[nf][2] = -1e30f;
        if (cg + 1 > r1g) sc[nf][3] = -1e30f;
      }
    }

    float mx0 = sc[0][0], mx1 = sc[0][2];
#pragma unroll
    for (int nf = 0; nf < 8; nf++) {
      mx0 = fmaxf(mx0, fmaxf(sc[nf][0], sc[nf][1]));
      mx1 = fmaxf(mx1, fmaxf(sc[nf][2], sc[nf][3]));
    }
    mx0 = fmaxf(mx0, __shfl_xor_sync(0xffffffffu, mx0, 1));
    mx0 = fmaxf(mx0, __shfl_xor_sync(0xffffffffu, mx0, 2));
    mx1 = fmaxf(mx1, __shfl_xor_sync(0xffffffffu, mx1, 1));
    mx1 = fmaxf(mx1, __shfl_xor_sync(0xffffffffu, mx1, 2));
    float mn0 = fmaxf(m0, mx0), mn1 = fmaxf(m1, mx1);
    float cr0 = __expf(m0 - mn0), cr1 = __expf(m1 - mn1);
    m0 = mn0; m1 = mn1;
    float rs0 = 0.f, rs1 = 0.f;
#pragma unroll
    for (int nf = 0; nf < 8; nf++) {
      float p00 = __expf(sc[nf][0] - mn0);
      float p01 = __expf(sc[nf][1] - mn0);
      float p10 = __expf(sc[nf][2] - mn1);
      float p11 = __expf(sc[nf][3] - mn1);
      rs0 += p00 + p01;
      rs1 += p10 + p11;
      *(float2*)(Pw + lr * PS_S + nf * 8 + 2 * lc) = make_float2(p00, p01);
      *(float2*)(Pw + (lr + 8) * PS_S + nf * 8 + 2 * lc) =
          make_float2(p10, p11);
    }
    rs0 += __shfl_xor_sync(0xffffffffu, rs0, 1);
    rs0 += __shfl_xor_sync(0xffffffffu, rs0, 2);
    rs1 += __shfl_xor_sync(0xffffffffu, rs1, 1);
    rs1 += __shfl_xor_sync(0xffffffffu, rs1, 2);
    l0 = l0 * cr0 + rs0;
    l1 = l1 * cr1 + rs1;
#pragma unroll
    for (int nf = 0; nf < 16; nf++) {
      o[nf][0] *= cr0; o[nf][1] *= cr0;
      o[nf][2] *= cr1; o[nf][3] *= cr1;
    }
    __syncwarp();

#pragma unroll
    for (int ks = 0; ks < 8; ks++) {
      const int kb = ks * 8;
      unsigned a0 = __float_as_uint(Pw[lr * PS_S + kb + lc]);
      unsigned a1 = __float_as_uint(Pw[(lr + 8) * PS_S + kb + lc]);
      unsigned a2 = __float_as_uint(Pw[lr * PS_S + kb + lc + 4]);
      unsigned a3 = __float_as_uint(Pw[(lr + 8) * PS_S + kb + lc + 4]);
#pragma unroll
      for (int nf = 0; nf < 16; nf++) {
        unsigned b0 = __float_as_uint(Vs[(kb + lc) * VS_S + nf * 8 + lr]);
        unsigned b1 = __float_as_uint(Vs[(kb + lc + 4) * VS_S + nf * 8 + lr]);
        mma_tf32(o[nf][0], o[nf][1], o[nf][2], o[nf][3], a0, a1, a2, a3, b0,
                 b1);
      }
    }
    __syncwarp();
  }

  // ---- epilogue: normalize, write ctx as fp16 [B*S][DM] ----
  const int b = bh >> 4, h = bh & 15;
  const float inv0 = 1.f / l0, inv1 = 1.f / l1;
  const int r0g = q0 + wm + lr, r1g = r0g + 8;
  __half* base0 = g_ctxh + (size_t)(b * SEQ + r0g) * DM + h * DH;
  __half* base1 = g_ctxh + (size_t)(b * SEQ + r1g) * DM + h * DH;
#pragma unroll
  for (int nf = 0; nf < 16; nf++) {
    *(__half2*)(base0 + nf * 8 + 2 * lc) =
        __floats2half2_rn(o[nf][0] * inv0, o[nf][1] * inv0);
    *(__half2*)(base1 + nf * 8 + 2 * lc) =
        __floats2half2_rn(o[nf][2] * inv1, o[nf][3] * inv1);
  }
}

// ---------------------------------------------------------------------------
extern "C" void kernel_launch(void* const* d_in, const int* in_sizes, int n_in,
                              void* d_out, int out_size) {
  const float* x    = (const float*)d_in[0];
  const float* Wqkv = (const float*)d_in[1];
  const float* bqkv = (const float*)d_in[2];
  const float* Wout = (const float*)d_in[3];
  const float* bout = (const float*)d_in[4];
  float* out = (float*)d_out;

  cudaFuncSetAttribute(gemm_h_kernel<3 * DM, true, false>,
                       cudaFuncAttributeMaxDynamicSharedMemorySize, GEMM_SMEM);
  cudaFuncSetAttribute(gemm_h_kernel<DM, false, true>,
                       cudaFuncAttributeMaxDynamicSharedMemorySize, GEMM_SMEM);
  cudaFuncSetAttribute(flash_mma_kernel,
                       cudaFuncAttributeMaxDynamicSharedMemorySize, FLASH_SMEM);

  // prepass: x -> fp16; weights -> transposed [N][K] fp16
  x_to_h_kernel<<<2048, 256>>>((const float4*)x, MTOK * DM / 4);
  transpose_h_kernel<3 * DM, 1>
      <<<dim3(3 * DM / 32, DM / 32), dim3(32, 8)>>>(Wqkv);
  transpose_h_kernel<DM, 2>
      <<<dim3(DM / 32, DM / 32), dim3(32, 8)>>>(Wout);

  gemm_h_kernel<3 * DM, true, false>
      <<<dim3(48, 32), 256, GEMM_SMEM>>>(bqkv, nullptr);
  flash_mma_kernel<<<dim3(16, 32), 256, FLASH_SMEM>>>();
  gemm_h_kernel<DM, false, true>
      <<<dim3(16, 32), 256, GEMM_SMEM>>>(bout, out);
}

// round 13
// speedup vs baseline: 6.7561x; 1.2393x over previous
#include <cuda_runtime.h>
#include <cuda_fp16.h>
#include <cstdint>
#include <math.h>

#define NB 2
#define NH 16
#define SEQ 2048
#define DH 128
#define DM 2048          // NH*DH
#define MTOK (NB*SEQ)    // 4096

// Scratch (static device allocations — allowed; no cudaMalloc anywhere)
__device__ __half g_qkv[(size_t)3 * NB * NH * SEQ * DH];  // [3][B][H][S][D] fp16
__device__ __half g_xh[(size_t)MTOK * DM];      // x fp16            [M][K]
__device__ __half g_wqkvh[(size_t)3 * DM * DM]; // W_qkv^T fp16      [N=6144][K]
__device__ __half g_wouth[(size_t)DM * DM];     // W_out^T fp16      [N=2048][K]
__device__ __half g_ctxh[(size_t)MTOK * DM];    // ctx fp16          [M][K]

// ---------------------------------------------------------------------------
// helpers
// ---------------------------------------------------------------------------
// fp16 mma m16n8k16: A row-major [16x16], B col-major [8 cols x 16 k], C f32
__device__ __forceinline__ void mma_f16(float& c0, float& c1, float& c2,
                                        float& c3, unsigned a0, unsigned a1,
                                        unsigned a2, unsigned a3, unsigned b0,
                                        unsigned b1) {
  asm volatile(
      "mma.sync.aligned.m16n8k16.row.col.f32.f16.f16.f32 "
      "{%0,%1,%2,%3},{%4,%5,%6,%7},{%8,%9},{%0,%1,%2,%3};\n"
      : "+f"(c0), "+f"(c1), "+f"(c2), "+f"(c3)
      : "r"(a0), "r"(a1), "r"(a2), "r"(a3), "r"(b0), "r"(b1));
}
__device__ __forceinline__ unsigned smem_u32(const void* p) {
  return (unsigned)__cvta_generic_to_shared(p);
}
#define CP16(dst_u32, gptr) \
  asm volatile("cp.async.cg.shared.global [%0], [%1], 16;\n" ::"r"(dst_u32), \
               "l"(gptr))
#define LDMATRIX_X4_TRANS(v0, v1, v2, v3, addr)                        \
  asm volatile(                                                        \
      "ldmatrix.sync.aligned.m8n8.x4.trans.shared.b16 {%0,%1,%2,%3}, " \
      "[%4];"                                                          \
      : "=r"(v0), "=r"(v1), "=r"(v2), "=r"(v3)                         \
      : "r"(addr))

__device__ __forceinline__ unsigned pack_h2(float a, float b) {
  __half2 h = __floats2half2_rn(a, b);
  return *(unsigned*)&h;
}

// ---------------------------------------------------------------------------
// Prepass 1: x (fp32) -> g_xh (fp16), layout unchanged
// ---------------------------------------------------------------------------
__global__ void x_to_h_kernel(const float4* __restrict__ src, int n4) {
  __half2* dst = (__half2*)g_xh;
  for (int i = blockIdx.x * blockDim.x + threadIdx.x; i < n4;
       i += gridDim.x * blockDim.x) {
    float4 v = src[i];
    dst[2 * i] = __floats2half2_rn(v.x, v.y);
    dst[2 * i + 1] = __floats2half2_rn(v.z, v.w);
  }
}

// ---------------------------------------------------------------------------
// Prepass 2: W [K=2048][NCOLS] fp32 -> W^T [NCOLS][2048] fp16
// ---------------------------------------------------------------------------
template <int NCOLS, int WHICH>
__global__ void transpose_h_kernel(const float* __restrict__ src) {
  __half* dst = (WHICH == 1) ? g_wqkvh : g_wouth;
  __shared__ float tile[32][33];
  const int n0 = blockIdx.x * 32, k0 = blockIdx.y * 32;
  const int tx = threadIdx.x, ty = threadIdx.y;  // 32 x 8
#pragma unroll
  for (int i = 0; i < 32; i += 8)
    tile[ty + i][tx] = src[(size_t)(k0 + ty + i) * NCOLS + n0 + tx];
  __syncthreads();
#pragma unroll
  for (int i = 0; i < 32; i += 8)
    dst[(size_t)(n0 + ty + i) * DM + k0 + tx] =
        __float2half_rn(tile[tx][ty + i]);
}

// ---------------------------------------------------------------------------
// FP16 tensor-core GEMM (passing since R12). QKV epilogue now writes fp16
// half2 directly into g_qkv (no tf32 rounding needed).
// ---------------------------------------------------------------------------
#define SH 72                    // halves per smem row
#define TILE_H (128 * SH)        // halves per tile (A or B)
#define GEMM_SMEM (2 * 2 * TILE_H * 2)  // 73728 B

template <int N, bool QKV_SCATTER, bool A_FROM_CTX>
__global__ __launch_bounds__(256, 2) void gemm_h_kernel(
    const float* __restrict__ bias, float* __restrict__ Cout) {
  extern __shared__ __half smh[];
  const __half* A = A_FROM_CTX ? g_ctxh : g_xh;
  const __half* Bw = QKV_SCATTER ? g_wqkvh : g_wouth;
  __half* AsBase = smh;
  __half* BsBase = smh + 2 * TILE_H;
  const int K = DM;
  const int bm = blockIdx.y * 128, bn = blockIdx.x * 128;
  const int tid = threadIdx.x;
  const int warp = tid >> 5, lane = tid & 31;
  const int wm = (warp & 1) * 64;
  const int wn = (warp >> 1) * 32;

  float acc[4][4][4];
#pragma unroll
  for (int mf = 0; mf < 4; mf++)
#pragma unroll
    for (int nf = 0; nf < 4; nf++)
#pragma unroll
      for (int i = 0; i < 4; i++) acc[mf][nf][i] = 0.f;

  auto load_tile = [&](int k0, int buf) {
    __half* as = AsBase + buf * TILE_H;
    __half* bs = BsBase + buf * TILE_H;
#pragma unroll
    for (int i = 0; i < 4; i++) {
      int cid = tid + i * 256;
      int row = cid >> 3, u = cid & 7;
      CP16(smem_u32(as + row * SH + u * 8),
           A + (size_t)(bm + row) * K + k0 + u * 8);
    }
#pragma unroll
    for (int i = 0; i < 4; i++) {
      int cid = tid + i * 256;
      int row = cid >> 3, u = cid & 7;
      CP16(smem_u32(bs + row * SH + u * 8),
           Bw + (size_t)(bn + row) * K + k0 + u * 8);
    }
    asm volatile("cp.async.commit_group;\n");
  };

  load_tile(0, 0);

  const int lr = lane >> 2, lc = lane & 3;

  for (int t = 0; t < K / 64; t++) {
    if (t + 1 < K / 64) {
      load_tile((t + 1) * 64, (t + 1) & 1);
      asm volatile("cp.async.wait_group 1;\n");
    } else {
      asm volatile("cp.async.wait_group 0;\n");
    }
    __syncthreads();

    const __half* as = AsBase + (t & 1) * TILE_H;
    const __half* bs = BsBase + (t & 1) * TILE_H;

#pragma unroll
    for (int ks = 0; ks < 4; ks++) {
      const int kh = ks * 16;
      unsigned a[4][4];
#pragma unroll
      for (int mf = 0; mf < 4; mf++) {
        const __half* ap = as + (wm + mf * 16 + lr) * SH + kh + 2 * lc;
        a[mf][0] = *(const unsigned*)(ap);
        a[mf][1] = *(const unsigned*)(ap + 8 * SH);
        a[mf][2] = *(const unsigned*)(ap + 8);
        a[mf][3] = *(const unsigned*)(ap + 8 * SH + 8);
      }
      unsigned b[4][2];
#pragma unroll
      for (int nf = 0; nf < 4; nf++) {
        const __half* bp = bs + (wn + nf * 8 + lr) * SH + kh + 2 * lc;
        b[nf][0] = *(const unsigned*)(bp);
        b[nf][1] = *(const unsigned*)(bp + 8);
      }
#pragma unroll
      for (int mf = 0; mf < 4; mf++)
#pragma unroll
        for (int nf = 0; nf < 4; nf++)
          mma_f16(acc[mf][nf][0], acc[mf][nf][1], acc[mf][nf][2],
                  acc[mf][nf][3], a[mf][0], a[mf][1], a[mf][2], a[mf][3],
                  b[nf][0], b[nf][1]);
    }
    __syncthreads();
  }

#pragma unroll
  for (int mf = 0; mf < 4; mf++) {
#pragma unroll
    for (int nf = 0; nf < 4; nf++) {
      int r0 = bm + wm + mf * 16 + lr;
      int c0 = bn + wn + nf * 8 + 2 * lc;
      float bia0 = bias[c0], bia1 = bias[c0 + 1];
      float v00 = acc[mf][nf][0] + bia0, v01 = acc[mf][nf][1] + bia1;
      float v10 = acc[mf][nf][2] + bia0, v11 = acc[mf][nf][3] + bia1;
      if (QKV_SCATTER) {
        int which = c0 >> 11, rr = c0 & 2047;
        int h = rr >> 7, d = rr & 127;
#pragma unroll
        for (int rv = 0; rv < 2; rv++) {
          int m = r0 + rv * 8;
          int b = m >> 11, sidx = m & 2047;
          __half* dst = g_qkv +
                        (size_t)(((which * NB + b) * NH + h) * SEQ + sidx) *
                            DH +
                        d;
          *(__half2*)dst = rv ? __floats2half2_rn(v10, v11)
                              : __floats2half2_rn(v00, v01);
        }
      } else {
        *(float2*)(Cout + (size_t)r0 * N + c0) = make_float2(v00, v01);
        *(float2*)(Cout + (size_t)(r0 + 8) * N + c0) = make_float2(v10, v11);
      }
    }
  }
}

// ---------------------------------------------------------------------------
// FP16 flash attention. CTA: 128 q x 64 k/iter, 8 warps (16 q-rows each),
// warp-private online softmax. P stays in registers (QK^T C-frag == PV
// A-frag for m16n8k16). V B-frags via ldmatrix.x4.trans.
// Strides 136 halves = 68 words (≡4 mod 32): all frag loads conflict-free.
// ---------------------------------------------------------------------------
#define FQ_S 136
#define FK_S 136
#define FV_S 136
#define FLASH_SMEM ((128 * FQ_S + 64 * FK_S + 64 * FV_S) * 2)  // 69632 B

__global__ __launch_bounds__(256, 2) void flash_h_kernel() {
  extern __shared__ __half smh[];
  __half* Qs = smh;                    // [128][136]
  __half* Ks = Qs + 128 * FQ_S;        // [64][136]
  __half* Vs = Ks + 64 * FK_S;         // [64][136]

  const int bh = blockIdx.y;
  const int qt = gridDim.x - 1 - blockIdx.x;  // longest CTAs first
  const int q0 = qt * 128;
  const __half* Qg = g_qkv + (size_t)bh * SEQ * DH + (size_t)q0 * DH;
  const __half* Kg = g_qkv + (size_t)(32 + bh) * SEQ * DH;
  const __half* Vg = g_qkv + (size_t)(64 + bh) * SEQ * DH;
  const int tid = threadIdx.x;
  const int warp = tid >> 5, lane = tid & 31;
  const int lr = lane >> 2, lc = lane & 3;
  const int wm = warp * 16;

  // Q tile: 128 rows x 16 chunks (8 halves) = 2048 chunks -> 8 per thread
#pragma unroll
  for (int u = 0; u < 8; u++) {
    int cid = tid + u * 256;
    int r = cid >> 4, c = (cid & 15) * 8;
    CP16(smem_u32(Qs + r * FQ_S + c), Qg + (size_t)r * DH + c);
  }
  asm volatile("cp.async.commit_group;\n");

  // per-lane ldmatrix.x4 row-pointer offset (halves):
  // sel 0..3 -> matrices (k0-7,n0),(k8-15,n0),(k0-7,n0+8),(k8-15,n0+8)
  const int lsel = lane >> 3, lrow = lane & 7;
  const unsigned ldm_off =
      (unsigned)((lrow + 8 * (lsel & 1)) * FV_S + 8 * (lsel >> 1));

  float o[16][4];
#pragma unroll
  for (int nf = 0; nf < 16; nf++)
#pragma unroll
    for (int i = 0; i < 4; i++) o[nf][i] = 0.f;
  float m0 = -1e30f, m1 = -1e30f, l0 = 0.f, l1 = 0.f;

  const float scale = 0.08838834764831845f;  // 1/sqrt(128)
  const int nkt = 2 * qt + 2;

  for (int kt = 0; kt < nkt; kt++) {
    const int k0 = kt * 64;
    __syncthreads();  // prior iter's Ks/Vs reads done
    // K,V tiles: 64 rows x 16 chunks each = 1024 -> 4+4 per thread
#pragma unroll
    for (int u = 0; u < 4; u++) {
      int cid = tid + u * 256;
      int r = cid >> 4, c = (cid & 15) * 8;
      CP16(smem_u32(Ks + r * FK_S + c), Kg + (size_t)(k0 + r) * DH + c);
      CP16(smem_u32(Vs + r * FV_S + c), Vg + (size_t)(k0 + r) * DH + c);
    }
    asm volatile("cp.async.commit_group;\ncp.async.wait_group 0;\n");
    __syncthreads();

    // ---- S = Q @ K^T (8 k16-steps over d=128) ----
    float sc[8][4];
#pragma unroll
    for (int nf = 0; nf < 8; nf++)
#pragma unroll
      for (int i = 0; i < 4; i++) sc[nf][i] = 0.f;
#pragma unroll
    for (int ks = 0; ks < 8; ks++) {
      const int kh = ks * 16;
      const __half* ap = Qs + (wm + lr) * FQ_S + kh + 2 * lc;
      unsigned a0 = *(const unsigned*)(ap);
      unsigned a1 = *(const unsigned*)(ap + 8 * FQ_S);
      unsigned a2 = *(const unsigned*)(ap + 8);
      unsigned a3 = *(const unsigned*)(ap + 8 * FQ_S + 8);
#pragma unroll
      for (int nf = 0; nf < 8; nf++) {
        const __half* bp = Ks + (nf * 8 + lr) * FK_S + kh + 2 * lc;
        unsigned b0 = *(const unsigned*)(bp);
        unsigned b1 = *(const unsigned*)(bp + 8);
        mma_f16(sc[nf][0], sc[nf][1], sc[nf][2], sc[nf][3], a0, a1, a2, a3,
                b0, b1);
      }
    }
#pragma unroll
    for (int nf = 0; nf < 8; nf++)
#pragma unroll
      for (int i = 0; i < 4; i++) sc[nf][i] *= scale;

    // ---- causal mask ----
    const int r0g = q0 + wm + lr, r1g = r0g + 8;
    if (k0 + 63 > r0g) {
#pragma unroll
      for (int nf = 0; nf < 8; nf++) {
        int cg = k0 + nf * 8 + 2 * lc;
        if (cg > r0g) sc[nf][0] = -1e30f;
        if (cg + 1 > r0g) sc[nf][1] = -1e30f;
        if (cg > r1g) sc[nf][2] = -1e30f;
        if (cg + 1 > r1g) sc[nf][3] = -1e30f;
      }
    }

    // ---- online softmax (warp-private rows) ----
    float mx0 = sc[0][0], mx1 = sc[0][2];
#pragma unroll
    for (int nf = 0; nf < 8; nf++) {
      mx0 = fmaxf(mx0, fmaxf(sc[nf][0], sc[nf][1]));
      mx1 = fmaxf(mx1, fmaxf(sc[nf][2], sc[nf][3]));
    }
    mx0 = fmaxf(mx0, __shfl_xor_sync(0xffffffffu, mx0, 1));
    mx0 = fmaxf(mx0, __shfl_xor_sync(0xffffffffu, mx0, 2));
    mx1 = fmaxf(mx1, __shfl_xor_sync(0xffffffffu, mx1, 1));
    mx1 = fmaxf(mx1, __shfl_xor_sync(0xffffffffu, mx1, 2));
    float mn0 = fmaxf(m0, mx0), mn1 = fmaxf(m1, mx1);
    float cr0 = __expf(m0 - mn0), cr1 = __expf(m1 - mn1);
    m0 = mn0; m1 = mn1;
    float rs0 = 0.f, rs1 = 0.f;
    unsigned ph[8][2];  // P as half2: [nf](rows lr / lr+8)
#pragma unroll
    for (int nf = 0; nf < 8; nf++) {
      float p00 = __expf(sc[nf][0] - mn0);
      float p01 = __expf(sc[nf][1] - mn0);
      float p10 = __expf(sc[nf][2] - mn1);
      float p11 = __expf(sc[nf][3] - mn1);
      rs0 += p00 + p01;
      rs1 += p10 + p11;
      ph[nf][0] = pack_h2(p00, p01);
      ph[nf][1] = pack_h2(p10, p11);
    }
    rs0 += __shfl_xor_sync(0xffffffffu, rs0, 1);
    rs0 += __shfl_xor_sync(0xffffffffu, rs0, 2);
    rs1 += __shfl_xor_sync(0xffffffffu, rs1, 1);
    rs1 += __shfl_xor_sync(0xffffffffu, rs1, 2);
    l0 = l0 * cr0 + rs0;
    l1 = l1 * cr1 + rs1;
#pragma unroll
    for (int nf = 0; nf < 16; nf++) {
      o[nf][0] *= cr0; o[nf][1] *= cr0;
      o[nf][2] *= cr1; o[nf][3] *= cr1;
    }

    // ---- O += P @ V ----
    // P C-frag == A-frag: k-step j uses ph[2j] (k 16j..+7) and ph[2j+1].
    // V B-frags via ldmatrix.x4.trans on Vs[kk][d].
#pragma unroll
    for (int j = 0; j < 4; j++) {
      unsigned pa0 = ph[2 * j][0], pa1 = ph[2 * j][1];
      unsigned pa2 = ph[2 * j + 1][0], pa3 = ph[2 * j + 1][1];
      const unsigned vbase =
          smem_u32(Vs) + 2 * ((unsigned)(16 * j * FV_S) + ldm_off);
#pragma unroll
      for (int nfp = 0; nfp < 8; nfp++) {
        unsigned v0, v1, v2, v3;
        LDMATRIX_X4_TRANS(v0, v1, v2, v3, vbase + 2 * (16 * nfp));
        mma_f16(o[2 * nfp][0], o[2 * nfp][1], o[2 * nfp][2], o[2 * nfp][3],
                pa0, pa1, pa2, pa3, v0, v1);
        mma_f16(o[2 * nfp + 1][0], o[2 * nfp + 1][1], o[2 * nfp + 1][2],
                o[2 * nfp + 1][3], pa0, pa1, pa2, pa3, v2, v3);
      }
    }
  }

  // ---- epilogue: normalize, write ctx fp16 [B*S][DM] ----
  const int b = bh >> 4, h = bh & 15;
  const float inv0 = 1.f / l0, inv1 = 1.f / l1;
  const int r0g = q0 + wm + lr, r1g = r0g + 8;
  __half* base0 = g_ctxh + (size_t)(b * SEQ + r0g) * DM + h * DH;
  __half* base1 = g_ctxh + (size_t)(b * SEQ + r1g) * DM + h * DH;
#pragma unroll
  for (int nf = 0; nf < 16; nf++) {
    *(__half2*)(base0 + nf * 8 + 2 * lc) =
        __floats2half2_rn(o[nf][0] * inv0, o[nf][1] * inv0);
    *(__half2*)(base1 + nf * 8 + 2 * lc) =
        __floats2half2_rn(o[nf][2] * inv1, o[nf][3] * inv1);
  }
}

// ---------------------------------------------------------------------------
extern "C" void kernel_launch(void* const* d_in, const int* in_sizes, int n_in,
                              void* d_out, int out_size) {
  const float* x    = (const float*)d_in[0];
  const float* Wqkv = (const float*)d_in[1];
  const float* bqkv = (const float*)d_in[2];
  const float* Wout = (const float*)d_in[3];
  const float* bout = (const float*)d_in[4];
  float* out = (float*)d_out;

  cudaFuncSetAttribute(gemm_h_kernel<3 * DM, true, false>,
                       cudaFuncAttributeMaxDynamicSharedMemorySize, GEMM_SMEM);
  cudaFuncSetAttribute(gemm_h_kernel<DM, false, true>,
                       cudaFuncAttributeMaxDynamicSharedMemorySize, GEMM_SMEM);
  cudaFuncSetAttribute(flash_h_kernel,
                       cudaFuncAttributeMaxDynamicSharedMemorySize, FLASH_SMEM);

  // prepass: x -> fp16; weights -> transposed [N][K] fp16
  x_to_h_kernel<<<2048, 256>>>((const float4*)x, MTOK * DM / 4);
  transpose_h_kernel<3 * DM, 1>
      <<<dim3(3 * DM / 32, DM / 32), dim3(32, 8)>>>(Wqkv);
  transpose_h_kernel<DM, 2>
      <<<dim3(DM / 32, DM / 32), dim3(32, 8)>>>(Wout);

  gemm_h_kernel<3 * DM, true, false>
      <<<dim3(48, 32), 256, GEMM_SMEM>>>(bqkv, nullptr);
  flash_h_kernel<<<dim3(16, 32), 256, FLASH_SMEM>>>();
  gemm_h_kernel<DM, false, true>
      <<<dim3(16, 32), 256, GEMM_SMEM>>>(bout, out);
}